// round 3
// baseline (speedup 1.0000x reference)
#include <cuda_runtime.h>
#include <cuda_bf16.h>
#include <math.h>
#include <float.h>
#include <cub/block/block_radix_sort.cuh>

#define NN   16384
#define PER  512
#define NGR  32
#define EE   262144
#define CAP  16384      // per-graph edge capacity (2^14)
#define CAPB 14
#define FMAX 600

// ----------------------------- scratch (device globals) -----------------------
__device__ float g_X[NN * FMAX];   // level input features / pooled output
__device__ float g_B[NN * FMAX];   // h = X @ W
__device__ float g_C[NN * FMAX];   // conv output
__device__ float g_na[NN], g_nb[NN];
__device__ float g_dinv[NN], g_cself[NN];
__device__ float g_deg[NN];
__device__ int   g_hasself[NN];
__device__ unsigned int g_mxu[NN];
__device__ float g_den[NN];
__device__ int   g_cluster[NN];
__device__ float g_nscore[NN];
__device__ unsigned char g_nvalid[NN];

__device__ int g_srcA[NGR * CAP], g_dstA[NGR * CAP];
__device__ int g_srcB[NGR * CAP], g_dstB[NGR * CAP];
__device__ int g_cntA[NGR], g_cntB[NGR];
__device__ int g_eidx[NGR * CAP];          // stable-tie index (orig order)
__device__ float g_eraw[NGR * CAP];
__device__ float g_eex[NGR * CAP];
__device__ float g_escore[NGR * CAP];
__device__ unsigned long long g_ekey[NGR * CAP];
__device__ int g_eorder[NGR * CAP];        // rank -> slot
__device__ unsigned char g_echosen[NGR * CAP];  // by rank
__device__ float g_pool[NGR * FMAX];

// ----------------------------- helpers ---------------------------------------
__device__ __forceinline__ unsigned enc_f(float f) {
    unsigned u = __float_as_uint(f);
    return (u & 0x80000000u) ? ~u : (u | 0x80000000u);
}
__device__ __forceinline__ float dec_f(unsigned u) {
    unsigned v = (u & 0x80000000u) ? (u & 0x7FFFFFFFu) : ~u;
    return __uint_as_float(v);
}

// ----------------------------- init / ingest ----------------------------------
__global__ void k_init0() {
    int i = blockIdx.x * blockDim.x + threadIdx.x;
    if (i < NN) g_nvalid[i] = 1;
    if (i < NGR) g_cntA[i] = 0;
}

__global__ void k_ingest(const int* __restrict__ ei) {
    int e = blockIdx.x * blockDim.x + threadIdx.x;
    if (e >= EE) return;
    int s = ei[e], d = ei[EE + e];
    int g = s >> 9;
    int pos = atomicAdd(&g_cntA[g], 1);
    if (pos < CAP) {
        g_srcA[g * CAP + pos] = s;
        g_dstA[g * CAP + pos] = d;
        g_eidx[g * CAP + pos] = e;
    }
}

// ----------------------------- per-level node/edge kernels --------------------
__global__ void k_node_init() {
    int i = blockIdx.x * blockDim.x + threadIdx.x;
    if (i >= NN) return;
    g_deg[i] = 0.f; g_hasself[i] = 0;
    g_mxu[i] = 0u;  g_den[i] = 0.f;
    g_cluster[i] = i; g_nscore[i] = 1.f;
}

__global__ void k_edge_deg(int inA) {
    int tid = blockIdx.x * blockDim.x + threadIdx.x;
    if (tid >= NGR * CAP) return;
    const int* src = inA ? g_srcA : g_srcB;
    const int* dst = inA ? g_dstA : g_dstB;
    const int* cnt = inA ? g_cntA : g_cntB;
    int g = tid >> CAPB, slot = tid & (CAP - 1);
    if (slot >= cnt[g]) return;
    int s = src[tid], d = dst[tid];
    atomicAdd(&g_deg[d], 1.f);
    if (s == d) g_hasself[d] = 1;
}

__global__ void k_node_norm() {
    int i = blockIdx.x * blockDim.x + threadIdx.x;
    if (i >= NN) return;
    float add = g_hasself[i] ? 0.f : 1.f;
    float t = g_deg[i] + add;
    g_dinv[i] = rsqrtf(t);
    g_cself[i] = add / t;
}

__global__ void k_cinit(const float* __restrict__ bias, int F) {
    int tid = blockIdx.x * blockDim.x + threadIdx.x;
    if (tid >= NN * F) return;
    int i = tid / F, f = tid - i * F;
    g_C[tid] = g_cself[i] * g_B[tid] + bias[f];
}

__global__ void k_agg(int inA, int F) {
    const int* src = inA ? g_srcA : g_srcB;
    const int* dst = inA ? g_dstA : g_dstB;
    const int* cnt = inA ? g_cntA : g_cntB;
    int gt = blockIdx.x * blockDim.x + threadIdx.x;
    int warp = gt >> 5, lane = gt & 31;
    int nw = (gridDim.x * blockDim.x) >> 5;
    for (int sl = warp; sl < NGR * CAP; sl += nw) {
        int g = sl >> CAPB, slot = sl & (CAP - 1);
        if (slot >= cnt[g]) continue;
        int s = src[sl], d = dst[sl];
        float nrm = g_dinv[s] * g_dinv[d];
        const float* bs = &g_B[s * F];
        float* cd = &g_C[d * F];
        for (int f = lane; f < F; f += 32) atomicAdd(&cd[f], nrm * bs[f]);
    }
}

__global__ void k_nodedot(const float* __restrict__ Pw, int F) {
    int gt = blockIdx.x * blockDim.x + threadIdx.x;
    int node = gt >> 5, lane = gt & 31;
    if (node >= NN) return;
    const float* c = &g_C[node * F];
    float a = 0.f, b = 0.f;
    for (int f = lane; f < F; f += 32) {
        float v = c[f];
        a += v * Pw[f];
        b += v * Pw[F + f];
    }
    for (int o = 16; o > 0; o >>= 1) {
        a += __shfl_down_sync(0xFFFFFFFFu, a, o);
        b += __shfl_down_sync(0xFFFFFFFFu, b, o);
    }
    if (lane == 0) { g_na[node] = a; g_nb[node] = b; }
}

__global__ void k_edge_raw(int inA, const float* __restrict__ Pb) {
    int tid = blockIdx.x * blockDim.x + threadIdx.x;
    if (tid >= NGR * CAP) return;
    const int* src = inA ? g_srcA : g_srcB;
    const int* dst = inA ? g_dstA : g_dstB;
    const int* cnt = inA ? g_cntA : g_cntB;
    int g = tid >> CAPB, slot = tid & (CAP - 1);
    if (slot >= cnt[g]) return;
    float raw = g_na[src[tid]] + g_nb[dst[tid]] + Pb[0];
    g_eraw[tid] = raw;
    atomicMax(&g_mxu[dst[tid]], enc_f(raw));
}

__global__ void k_edge_ex(int inA) {
    int tid = blockIdx.x * blockDim.x + threadIdx.x;
    if (tid >= NGR * CAP) return;
    const int* dst = inA ? g_dstA : g_dstB;
    const int* cnt = inA ? g_cntA : g_cntB;
    int g = tid >> CAPB, slot = tid & (CAP - 1);
    if (slot >= cnt[g]) return;
    float mx = dec_f(g_mxu[dst[tid]]);
    float ex = expf(g_eraw[tid] - mx);
    g_eex[tid] = ex;
    atomicAdd(&g_den[dst[tid]], ex);
}

__global__ void k_edge_key(int inA) {
    int tid = blockIdx.x * blockDim.x + threadIdx.x;
    if (tid >= NGR * CAP) return;
    const int* dst = inA ? g_dstA : g_dstB;
    const int* cnt = inA ? g_cntA : g_cntB;
    int g = tid >> CAPB, slot = tid & (CAP - 1);
    if (slot >= cnt[g]) { g_ekey[tid] = ~0ull; return; }
    float sc = g_eex[tid] / fmaxf(g_den[dst[tid]], 1e-16f) + 0.1f;
    g_escore[tid] = sc;
    // ascending sort => descending score (inverted), then ascending orig index
    g_ekey[tid] = ((unsigned long long)(~enc_f(sc)) << 32)
                | ((unsigned long long)(unsigned)g_eidx[tid] << CAPB)
                | (unsigned)slot;
}

// ----------------------------- sorts (cub) ------------------------------------
constexpr int SORT_T = 512;
constexpr int SORT_I = 32;
using SortT = cub::BlockRadixSort<unsigned long long, SORT_T, SORT_I>;

__global__ void __launch_bounds__(SORT_T, 1) k_sort_score() {
    extern __shared__ char smraw[];
    typename SortT::TempStorage& temp = *reinterpret_cast<typename SortT::TempStorage*>(smraw);
    int g = blockIdx.x, base = g * CAP, t = threadIdx.x;
    unsigned long long keys[SORT_I];
#pragma unroll
    for (int i = 0; i < SORT_I; i++) keys[i] = g_ekey[base + t * SORT_I + i];
    SortT(temp).Sort(keys);
    __syncthreads();
#pragma unroll
    for (int i = 0; i < SORT_I; i++) {
        int r = t * SORT_I + i;
        g_eorder[base + r] = (int)(keys[i] & (CAP - 1));
        g_echosen[base + r] = 0;
    }
}

// ----------------------------- greedy matching --------------------------------
__global__ void __launch_bounds__(SORT_T, 1) k_match(int inA) {
    extern __shared__ char smraw[];
    unsigned* pairs = (unsigned*)smraw;                                   // CAP
    volatile unsigned char* marked = (unsigned char*)(smraw + CAP * 4);   // PER
    const int* src = inA ? g_srcA : g_srcB;
    const int* dst = inA ? g_dstA : g_dstB;
    const int* cntp = inA ? g_cntA : g_cntB;
    int g = blockIdx.x, base = g * CAP;
    int cnt = cntp[g]; if (cnt > CAP) cnt = CAP;
    for (int r = threadIdx.x; r < cnt; r += blockDim.x) {
        int slot = g_eorder[base + r];
        int s = src[base + slot] & (PER - 1);
        int d = dst[base + slot] & (PER - 1);
        pairs[r] = (unsigned)((s << 9) | d);
    }
    for (int p = threadIdx.x; p < PER; p += blockDim.x)
        marked[p] = g_nvalid[g * PER + p] ? 0 : 1;
    __syncthreads();
    if (threadIdx.x >= 32) return;
    int lane = threadIdx.x;
    for (int r0 = 0; r0 < cnt; r0 += 32) {
        bool cand = false;
        int r = r0 + lane;
        if (r < cnt) {
            unsigned pr = pairs[r];
            int s = pr >> 9, d = pr & 511;
            cand = (!marked[s]) && (!marked[d]);
        }
        unsigned bal = __ballot_sync(0xFFFFFFFFu, cand);
        if (bal) {
            if (lane == 0) {
                int lim = min(32, cnt - r0);
                for (int j = 0; j < lim; j++) {
                    unsigned pr = pairs[r0 + j];
                    int s = pr >> 9, d = pr & 511;
                    if (!marked[s] && !marked[d]) {
                        marked[s] = 1; marked[d] = 1;
                        g_echosen[base + r0 + j] = 1;
                    }
                }
            }
            __syncwarp();
        }
    }
}

__global__ void k_apply(int inA) {
    int tid = blockIdx.x * blockDim.x + threadIdx.x;
    if (tid >= NGR * CAP) return;
    const int* src = inA ? g_srcA : g_srcB;
    const int* dst = inA ? g_dstA : g_dstB;
    const int* cnt = inA ? g_cntA : g_cntB;
    int g = tid >> CAPB, r = tid & (CAP - 1);
    if (r >= cnt[g] || !g_echosen[tid]) return;
    int slot = g_eorder[tid];
    int s = src[g * CAP + slot], d = dst[g * CAP + slot];
    int rep = min(s, d), oth = max(s, d);
    g_nscore[rep] = g_escore[g * CAP + slot];
    if (s != d) {
        g_cluster[oth] = rep;
        g_nvalid[oth] = 0;
    }
}

// ----------------------------- pooling of features ----------------------------
__global__ void k_poolA(int F) {
    int tid = blockIdx.x * blockDim.x + threadIdx.x;
    if (tid >= NN * F) return;
    int i = tid / F;
    g_X[tid] = g_nvalid[i] ? g_C[tid] : 0.f;
}

__global__ void k_poolB(int inA, int F) {
    const int* src = inA ? g_srcA : g_srcB;
    const int* dst = inA ? g_dstA : g_dstB;
    const int* cnt = inA ? g_cntA : g_cntB;
    int gt = blockIdx.x * blockDim.x + threadIdx.x;
    int warp = gt >> 5, lane = gt & 31;
    int nw = (gridDim.x * blockDim.x) >> 5;
    for (int rg = warp; rg < NGR * CAP; rg += nw) {
        int g = rg >> CAPB, r = rg & (CAP - 1);
        if (r >= cnt[g] || !g_echosen[rg]) continue;
        int slot = g_eorder[rg];
        int s = src[g * CAP + slot], d = dst[g * CAP + slot];
        if (s == d) continue;
        int rep = min(s, d), oth = max(s, d);
        const float* co = &g_C[oth * F];
        float* xr = &g_X[rep * F];
        for (int f = lane; f < F; f += 32) atomicAdd(&xr[f], co[f]);
    }
}

__global__ void k_poolC(int F) {
    int tid = blockIdx.x * blockDim.x + threadIdx.x;
    if (tid >= NN * F) return;
    int i = tid / F;
    g_X[tid] = fmaxf(g_X[tid] * g_nscore[i], 0.f);   // scale + relu
}

// ----------------------------- coalesce edges to next level -------------------
__global__ void __launch_bounds__(SORT_T, 1) k_coalesce(int inA) {
    extern __shared__ char smraw[];
    int g = blockIdx.x, base = g * CAP, t = threadIdx.x;
    const int* src = inA ? g_srcA : g_srcB;
    const int* dst = inA ? g_dstA : g_dstB;
    const int* cntp = inA ? g_cntA : g_cntB;
    int* osrc = inA ? g_srcB : g_srcA;
    int* odst = inA ? g_dstB : g_dstA;
    int* ocnt = inA ? g_cntB : g_cntA;
    int cnt = cntp[g]; if (cnt > CAP) cnt = CAP;

    unsigned long long keys[SORT_I];
#pragma unroll
    for (int i = 0; i < SORT_I; i++) {
        int slot = t * SORT_I + i;
        if (slot < cnt) {
            int ns = g_cluster[src[base + slot]] & (PER - 1);
            int nd = g_cluster[dst[base + slot]] & (PER - 1);
            keys[i] = ((unsigned long long)(unsigned)((ns << 9) | nd) << CAPB) | (unsigned)slot;
        } else keys[i] = (1ull << 32);   // pad: pair-field = 2^18, sorts last
    }
    {
        typename SortT::TempStorage& temp = *reinterpret_cast<typename SortT::TempStorage*>(smraw);
        SortT(temp).Sort(keys, 0, 33);
    }
    __syncthreads();
    unsigned long long* lastk = (unsigned long long*)smraw;          // SORT_T
    int* scan = (int*)(smraw + SORT_T * sizeof(unsigned long long)); // SORT_T
    lastk[t] = keys[SORT_I - 1];
    __syncthreads();
    unsigned prevl = (t == 0) ? 0xFFFFFFFFu : (unsigned)(lastk[t - 1] >> CAPB);
    int flags[SORT_I]; int cl = 0;
#pragma unroll
    for (int i = 0; i < SORT_I; i++) {
        int r = t * SORT_I + i;
        unsigned lk = (unsigned)(keys[i] >> CAPB);
        bool f = (r < cnt) && (lk != prevl);
        flags[i] = f; cl += f; prevl = lk;
    }
    __syncthreads();
    scan[t] = cl;
    __syncthreads();
    for (int off = 1; off < SORT_T; off <<= 1) {
        int v = (t >= off) ? scan[t - off] : 0;
        __syncthreads();
        scan[t] += v;
        __syncthreads();
    }
    int pos = scan[t] - cl;
#pragma unroll
    for (int i = 0; i < SORT_I; i++) {
        if (flags[i]) {
            unsigned lk = (unsigned)(keys[i] >> CAPB);
            osrc[base + pos] = g * PER + ((lk >> 9) & 511);
            odst[base + pos] = g * PER + (lk & 511);
            g_eidx[base + pos] = pos;
            pos++;
        }
    }
    if (t == SORT_T - 1) ocnt[g] = scan[t];
}

// ----------------------------- GEMM (g_B = A @ W) ------------------------------
__global__ void k_gemm(const float* __restrict__ Ax, int K, int Nc, const float* __restrict__ W) {
    const float* A = Ax ? Ax : g_X;
    __shared__ float As[64][17];
    __shared__ float Bs[16][65];
    int t = threadIdx.x;
    int bm = blockIdx.y * 64, bn = blockIdx.x * 64;
    int tm = (t >> 4) << 2, tn = (t & 15) << 2;
    float acc[4][4];
#pragma unroll
    for (int i = 0; i < 4; i++)
#pragma unroll
        for (int j = 0; j < 4; j++) acc[i][j] = 0.f;

    for (int k0 = 0; k0 < K; k0 += 16) {
#pragma unroll
        for (int i = 0; i < 4; i++) {
            int lin = t + i * 256;
            int m = lin >> 4, kk = lin & 15;
            As[m][kk] = (k0 + kk < K) ? A[(bm + m) * K + k0 + kk] : 0.f;
            int k2 = lin >> 6, n2 = lin & 63;
            Bs[k2][n2] = (k0 + k2 < K && bn + n2 < Nc) ? W[(k0 + k2) * Nc + bn + n2] : 0.f;
        }
        __syncthreads();
#pragma unroll
        for (int kk = 0; kk < 16; kk++) {
            float a[4], b[4];
#pragma unroll
            for (int i = 0; i < 4; i++) { a[i] = As[tm + i][kk]; b[i] = Bs[kk][tn + i]; }
#pragma unroll
            for (int i = 0; i < 4; i++)
#pragma unroll
                for (int j = 0; j < 4; j++) acc[i][j] += a[i] * b[j];
        }
        __syncthreads();
    }
#pragma unroll
    for (int i = 0; i < 4; i++)
#pragma unroll
        for (int j = 0; j < 4; j++)
            if (bn + tn + j < Nc) g_B[(bm + tm + i) * Nc + bn + tn + j] = acc[i][j];
}

// ----------------------------- readout ----------------------------------------
__global__ void k_maxpool() {
    int g = blockIdx.x, f = threadIdx.x;
    if (f >= 600) return;
    float m = -FLT_MAX;
    for (int p = 0; p < PER; p++) {
        int i = g * PER + p;
        if (g_nvalid[i]) m = fmaxf(m, g_X[i * 600 + f]);
    }
    g_pool[g * 600 + f] = m;
}

__global__ void k_mlp(const float* __restrict__ L1w, const float* __restrict__ L1b,
                      const float* __restrict__ L2w, const float* __restrict__ L2b,
                      const float* __restrict__ L3w, const float* __restrict__ L3b,
                      float* __restrict__ out) {
    __shared__ float z1[200];
    __shared__ float z2[20];
    __shared__ float z3[4];
    int g = blockIdx.x, t = threadIdx.x;
    if (t < 200) {
        float a = L1b[t];
        for (int k = 0; k < 600; k++) a += g_pool[g * 600 + k] * L1w[k * 200 + t];
        z1[t] = fmaxf(a, 0.f);
    }
    __syncthreads();
    if (t < 20) {
        float a = L2b[t];
        for (int k = 0; k < 200; k++) a += z1[k] * L2w[k * 20 + t];
        z2[t] = fmaxf(a, 0.f);
    }
    __syncthreads();
    if (t < 4) {
        float a = L3b[t];
        for (int k = 0; k < 20; k++) a += z2[k] * L3w[k * 4 + t];
        z3[t] = fmaxf(a, 0.f);
    }
    __syncthreads();
    if (t == 0) {
        float m = fmaxf(fmaxf(z3[0], z3[1]), fmaxf(z3[2], z3[3]));
        float e0 = expf(z3[0] - m), e1 = expf(z3[1] - m);
        float e2 = expf(z3[2] - m), e3 = expf(z3[3] - m);
        float s = e0 + e1 + e2 + e3;
        out[g * 4 + 0] = e0 / s;
        out[g * 4 + 1] = e1 / s;
        out[g * 4 + 2] = e2 / s;
        out[g * 4 + 3] = e3 / s;
    }
}

// ----------------------------- host orchestration ------------------------------
static void run_level(const float* X, int Fin, int Fout,
                      const float* W, const float* b,
                      const float* Pw, const float* Pb, int inA) {
    const size_t SORT_SMEM = sizeof(typename SortT::TempStorage);
    dim3 gg((Fout + 63) / 64, NN / 64);
    k_gemm<<<gg, 256>>>(X, Fin, Fout, W);
    k_node_init<<<64, 256>>>();
    k_edge_deg<<<(NGR * CAP) / 256, 256>>>(inA);
    k_node_norm<<<64, 256>>>();
    k_cinit<<<(NN * Fout + 255) / 256, 256>>>(b, Fout);
    k_agg<<<2048, 256>>>(inA, Fout);
    k_nodedot<<<(NN * 32) / 256, 256>>>(Pw, Fout);
    k_edge_raw<<<(NGR * CAP) / 256, 256>>>(inA, Pb);
    k_edge_ex<<<(NGR * CAP) / 256, 256>>>(inA);
    k_edge_key<<<(NGR * CAP) / 256, 256>>>(inA);
    k_sort_score<<<NGR, SORT_T, SORT_SMEM>>>();
    k_match<<<NGR, SORT_T, CAP * 4 + PER>>>(inA);
    k_apply<<<(NGR * CAP) / 256, 256>>>(inA);
    k_poolA<<<(NN * Fout + 255) / 256, 256>>>(Fout);
    k_poolB<<<2048, 256>>>(inA, Fout);
    k_poolC<<<(NN * Fout + 255) / 256, 256>>>(Fout);
    k_coalesce<<<NGR, SORT_T, SORT_SMEM>>>(inA);
}

extern "C" void kernel_launch(void* const* d_in, const int* in_sizes, int n_in,
                              void* d_out, int out_size) {
    (void)in_sizes; (void)n_in; (void)out_size;
    const float* x   = (const float*)d_in[0];
    const int*   ei  = (const int*)d_in[1];
    // d_in[2] = batch (node i -> graph i/512, recomputed implicitly)
    const float* W1  = (const float*)d_in[3];
    const float* b1  = (const float*)d_in[4];
    const float* W2  = (const float*)d_in[5];
    const float* b2  = (const float*)d_in[6];
    const float* W3  = (const float*)d_in[7];
    const float* b3  = (const float*)d_in[8];
    const float* P1w = (const float*)d_in[9];
    const float* P1b = (const float*)d_in[10];
    const float* P2w = (const float*)d_in[11];
    const float* P2b = (const float*)d_in[12];
    const float* P3w = (const float*)d_in[13];
    const float* P3b = (const float*)d_in[14];
    const float* L1w = (const float*)d_in[15];
    const float* L1b = (const float*)d_in[16];
    const float* L2w = (const float*)d_in[17];
    const float* L2b = (const float*)d_in[18];
    const float* L3w = (const float*)d_in[19];
    const float* L3b = (const float*)d_in[20];
    float* out = (float*)d_out;

    const size_t SORT_SMEM = sizeof(typename SortT::TempStorage);
    cudaFuncSetAttribute(k_sort_score, cudaFuncAttributeMaxDynamicSharedMemorySize, (int)SORT_SMEM);
    cudaFuncSetAttribute(k_coalesce,   cudaFuncAttributeMaxDynamicSharedMemorySize, (int)SORT_SMEM);
    cudaFuncSetAttribute(k_match,      cudaFuncAttributeMaxDynamicSharedMemorySize, CAP * 4 + PER);

    k_init0<<<64, 256>>>();
    k_ingest<<<EE / 256, 256>>>(ei);

    run_level(x,       107, 200, W1, b1, P1w, P1b, 1);  // edges A -> B
    run_level(nullptr, 200, 400, W2, b2, P2w, P2b, 0);  // edges B -> A
    run_level(nullptr, 400, 600, W3, b3, P3w, P3b, 1);  // edges A -> B

    k_maxpool<<<NGR, 600>>>();
    k_mlp<<<NGR, 256>>>(L1w, L1b, L2w, L2b, L3w, L3b, out);
}

// round 4
// speedup vs baseline: 1.2012x; 1.2012x over previous
#include <cuda_runtime.h>
#include <cuda_bf16.h>
#include <math.h>
#include <float.h>
#include <cub/block/block_radix_sort.cuh>

#define NN   16384
#define PER  512
#define NGR  32
#define EE   262144
#define CAP  16384      // per-graph edge capacity (2^14)
#define CAPB 14
#define FMAX 600

// ----------------------------- scratch (device globals) -----------------------
__device__ float g_X[NN * FMAX];   // level input features / pooled output
__device__ float g_B[NN * FMAX];   // h = X @ W
__device__ float g_C[NN * FMAX];   // conv output
__device__ float g_na[NN], g_nb[NN];
__device__ float g_dinv[NN], g_cself[NN];
__device__ float g_den[NN];
__device__ int   g_cluster[NN];
__device__ float g_nscore[NN];
__device__ unsigned char g_nvalid[NN];
__device__ int   g_rs[NN], g_re[NN];        // CSR row range in dst-sorted order

__device__ int g_srcA[NGR * CAP], g_dstA[NGR * CAP];
__device__ int g_srcB[NGR * CAP], g_dstB[NGR * CAP];
__device__ int g_cntA[NGR], g_cntB[NGR];
__device__ int g_eidx[NGR * CAP];           // stable-tie index (orig order), by slot
__device__ int g_sslot[NGR * CAP];          // dst-sorted rank -> slot
__device__ int g_ssrc[NGR * CAP];           // dst-sorted rank -> global src node
__device__ float g_eex[NGR * CAP];          // by dst-sorted rank
__device__ float g_escore[NGR * CAP];       // by slot
__device__ unsigned long long g_ekey[NGR * CAP];  // by dst-sorted rank
__device__ int g_eorder[NGR * CAP];         // score-rank -> slot
__device__ unsigned char g_echosen[NGR * CAP];    // by score-rank
__device__ float g_pool[NGR * FMAX];

// ----------------------------- helpers ---------------------------------------
__device__ __forceinline__ unsigned enc_f(float f) {
    unsigned u = __float_as_uint(f);
    return (u & 0x80000000u) ? ~u : (u | 0x80000000u);
}

__device__ __forceinline__ unsigned long long pack2(float x, float y) {
    unsigned long long r;
    asm("mov.b64 %0, {%1, %2};" : "=l"(r) : "f"(x), "f"(y));
    return r;
}
__device__ __forceinline__ void unpack2(float& x, float& y, unsigned long long v) {
    asm("mov.b64 {%0, %1}, %2;" : "=f"(x), "=f"(y) : "l"(v));
}
__device__ __forceinline__ unsigned long long fma2(unsigned long long a,
                                                   unsigned long long b,
                                                   unsigned long long c) {
    unsigned long long d;
    asm("fma.rn.f32x2 %0, %1, %2, %3;" : "=l"(d) : "l"(a), "l"(b), "l"(c));
    return d;
}

// ----------------------------- init / ingest ----------------------------------
__global__ void k_init0() {
    int i = blockIdx.x * blockDim.x + threadIdx.x;
    if (i < NN) g_nvalid[i] = 1;
    if (i < NGR) g_cntA[i] = 0;
}

__global__ void k_ingest(const int* __restrict__ ei) {
    int e = blockIdx.x * blockDim.x + threadIdx.x;
    if (e >= EE) return;
    int s = ei[e], d = ei[EE + e];
    int g = s >> 9;
    int pos = atomicAdd(&g_cntA[g], 1);
    if (pos < CAP) {
        g_srcA[g * CAP + pos] = s;
        g_dstA[g * CAP + pos] = d;
        g_eidx[g * CAP + pos] = e;
    }
}

__global__ void k_node_init() {
    int i = blockIdx.x * blockDim.x + threadIdx.x;
    if (i >= NN) return;
    g_cluster[i] = i;
    g_nscore[i] = 1.f;
}

// ----------------------------- dst-sort + CSR (per-graph CTA) ------------------
constexpr int SORT_T = 512;
constexpr int SORT_I = 32;
using SortT64 = cub::BlockRadixSort<unsigned long long, SORT_T, SORT_I>;
using SortT32 = cub::BlockRadixSort<unsigned, SORT_T, SORT_I>;

__global__ void __launch_bounds__(SORT_T, 1) k_sortdst(int inA) {
    extern __shared__ char smraw[];
    const int* src = inA ? g_srcA : g_srcB;
    const int* dst = inA ? g_dstA : g_dstB;
    const int* cntp = inA ? g_cntA : g_cntB;
    int g = blockIdx.x, base = g * CAP, t = threadIdx.x;
    int cnt = cntp[g]; if (cnt > CAP) cnt = CAP;

    unsigned keys[SORT_I];
#pragma unroll
    for (int i = 0; i < SORT_I; i++) {
        int slot = t * SORT_I + i;
        if (slot < cnt) {
            unsigned d = (unsigned)(dst[base + slot] & (PER - 1));
            keys[i] = (d << CAPB) | (unsigned)slot;
        } else {
            keys[i] = (512u << CAPB) | (unsigned)slot;   // pad sorts after all real d
        }
    }
    {
        typename SortT32::TempStorage& temp =
            *reinterpret_cast<typename SortT32::TempStorage*>(smraw);
        SortT32(temp).Sort(keys, CAPB, 24);
    }
    __syncthreads();
    unsigned short* d16 = (unsigned short*)smraw;   // reuse smem: CAP u16
#pragma unroll
    for (int i = 0; i < SORT_I; i++) {
        int r = t * SORT_I + i;
        unsigned k = keys[i];
        int slot = (int)(k & (CAP - 1));
        int d = (int)(k >> CAPB);
        if (r < cnt) {
            g_sslot[base + r] = slot;
            g_ssrc[base + r] = src[base + slot];
            d16[r] = (unsigned short)d;
        }
    }
    __syncthreads();
    if (t < PER) { g_rs[g * PER + t] = 0; g_re[g * PER + t] = 0; }
    __syncthreads();
    for (int r = t; r < cnt; r += SORT_T) {
        int d = d16[r];
        if (r == 0 || d16[r - 1] != d) g_rs[g * PER + d] = r;
        if (r == cnt - 1 || d16[r + 1] != d) g_re[g * PER + d] = r + 1;
    }
}

// per-dst degree / self-loop / norm — no atomics, deterministic
__global__ void k_degself() {
    int nid = blockIdx.x * blockDim.x + threadIdx.x;
    if (nid >= NN) return;
    int g = nid >> 9, base = g * CAP;
    int rs = g_rs[nid], re = g_re[nid];
    int selfv = 0;
    for (int r = rs; r < re; r++)
        if (g_ssrc[base + r] == nid) selfv = 1;
    float add = selfv ? 0.f : 1.f;
    float tdeg = (float)(re - rs) + add;
    g_dinv[nid] = rsqrtf(tdeg);
    g_cself[nid] = add / tdeg;
}

__global__ void k_cinit(const float* __restrict__ bias, int F) {
    int tid = blockIdx.x * blockDim.x + threadIdx.x;
    if (tid >= NN * F) return;
    int i = tid / F, f = tid - i * F;
    g_C[tid] = g_cself[i] * g_B[tid] + bias[f];
}

// CSR aggregation: warp per dst node, lane per feature, register accumulate
__global__ void k_aggcsr(int F) {
    int g = blockIdx.y;
    int f = blockIdx.x * 32 + (threadIdx.x & 31);
    int w = threadIdx.x >> 5;
    bool fv = (f < F);
    int base = g * CAP;
    for (int d = w; d < PER; d += 8) {
        int nid = g * PER + d;
        int rs = g_rs[nid], re = g_re[nid];
        if (rs >= re) continue;
        float acc = 0.f;
        for (int r = rs; r < re; r++) {
            int s = g_ssrc[base + r];
            float ds = g_dinv[s];
            float v = fv ? g_B[s * F + f] : 0.f;
            acc += ds * v;
        }
        if (fv) g_C[nid * F + f] += acc * g_dinv[nid];
    }
}

__global__ void k_nodedot(const float* __restrict__ Pw, int F) {
    int gt = blockIdx.x * blockDim.x + threadIdx.x;
    int node = gt >> 5, lane = gt & 31;
    if (node >= NN) return;
    const float* c = &g_C[node * F];
    float a = 0.f, b = 0.f;
    for (int f = lane; f < F; f += 32) {
        float v = c[f];
        a += v * Pw[f];
        b += v * Pw[F + f];
    }
    for (int o = 16; o > 0; o >>= 1) {
        a += __shfl_down_sync(0xFFFFFFFFu, a, o);
        b += __shfl_down_sync(0xFFFFFFFFu, b, o);
    }
    if (lane == 0) { g_na[node] = a; g_nb[node] = b; }
}

// per-dst softmax (max, den, score, sort key) — deterministic, no atomics
__global__ void k_maxden(const float* __restrict__ Pb) {
    int nid = blockIdx.x * blockDim.x + threadIdx.x;
    if (nid >= NN) return;
    int g = nid >> 9, base = g * CAP;
    int rs = g_rs[nid], re = g_re[nid];
    if (rs >= re) return;
    float nbd = g_nb[nid] + Pb[0];
    float mx = -FLT_MAX;
    for (int r = rs; r < re; r++)
        mx = fmaxf(mx, g_na[g_ssrc[base + r]] + nbd);
    float den = 0.f;
    for (int r = rs; r < re; r++) {
        float ex = expf(g_na[g_ssrc[base + r]] + nbd - mx);
        g_eex[base + r] = ex;
        den += ex;
    }
    den = fmaxf(den, 1e-16f);
    for (int r = rs; r < re; r++) {
        float sc = g_eex[base + r] / den + 0.1f;
        int slot = g_sslot[base + r];
        g_escore[base + slot] = sc;
        g_ekey[base + r] = ((unsigned long long)(~enc_f(sc)) << 32)
                         | ((unsigned long long)(unsigned)g_eidx[base + slot] << CAPB)
                         | (unsigned)slot;
    }
}

// ----------------------------- score sort (desc score, asc idx) ----------------
__global__ void __launch_bounds__(SORT_T, 1) k_sort_score(int inA) {
    extern __shared__ char smraw[];
    typename SortT64::TempStorage& temp =
        *reinterpret_cast<typename SortT64::TempStorage*>(smraw);
    const int* cntp = inA ? g_cntA : g_cntB;
    int g = blockIdx.x, base = g * CAP, t = threadIdx.x;
    int cnt = cntp[g]; if (cnt > CAP) cnt = CAP;
    unsigned long long keys[SORT_I];
#pragma unroll
    for (int i = 0; i < SORT_I; i++) {
        int r = t * SORT_I + i;
        keys[i] = (r < cnt) ? g_ekey[base + r] : ~0ull;
    }
    SortT64(temp).Sort(keys, CAPB, 64);
    __syncthreads();
#pragma unroll
    for (int i = 0; i < SORT_I; i++) {
        int r = t * SORT_I + i;
        g_eorder[base + r] = (int)(keys[i] & (CAP - 1));
        g_echosen[base + r] = 0;
    }
}

// ----------------------------- greedy matching (ballot-driven) -----------------
__global__ void __launch_bounds__(SORT_T, 1) k_match(int inA) {
    extern __shared__ char smraw[];
    unsigned* pairs = (unsigned*)smraw;                               // CAP
    unsigned char* marked = (unsigned char*)(smraw + CAP * 4);        // PER
    const int* src = inA ? g_srcA : g_srcB;
    const int* dst = inA ? g_dstA : g_dstB;
    const int* cntp = inA ? g_cntA : g_cntB;
    int g = blockIdx.x, base = g * CAP;
    int cnt = cntp[g]; if (cnt > CAP) cnt = CAP;
    for (int r = threadIdx.x; r < cnt; r += blockDim.x) {
        int slot = g_eorder[base + r];
        int s = src[base + slot] & (PER - 1);
        int d = dst[base + slot] & (PER - 1);
        pairs[r] = (unsigned)((s << 9) | d);
    }
    for (int p = threadIdx.x; p < PER; p += blockDim.x)
        marked[p] = g_nvalid[g * PER + p] ? 0 : 1;
    __syncthreads();
    if (threadIdx.x >= 32) return;
    int lane = threadIdx.x;
    for (int r0 = 0; r0 < cnt; r0 += 32) {
        int r = r0 + lane;
        int s = -1, d = -1;
        bool cand = false;
        if (r < cnt) {
            unsigned pr = pairs[r];
            s = pr >> 9; d = pr & 511;
            cand = (marked[s] == 0) && (marked[d] == 0);
        }
        unsigned bal = __ballot_sync(0xFFFFFFFFu, cand);
        while (bal) {
            int j = __ffs(bal) - 1;
            int sj = __shfl_sync(0xFFFFFFFFu, s, j);
            int dj = __shfl_sync(0xFFFFFFFFu, d, j);
            if (lane == j) {
                marked[s] = 1; marked[d] = 1;
                g_echosen[base + r] = 1;
            }
            bal &= ~(1u << j);
            bool kill = (s == sj || s == dj || d == sj || d == dj);
            bal &= ~__ballot_sync(0xFFFFFFFFu, kill);
        }
        __syncwarp();
    }
}

__global__ void k_apply(int inA) {
    int tid = blockIdx.x * blockDim.x + threadIdx.x;
    if (tid >= NGR * CAP) return;
    const int* src = inA ? g_srcA : g_srcB;
    const int* dst = inA ? g_dstA : g_dstB;
    const int* cnt = inA ? g_cntA : g_cntB;
    int g = tid >> CAPB, r = tid & (CAP - 1);
    if (r >= cnt[g] || !g_echosen[tid]) return;
    int slot = g_eorder[tid];
    int s = src[g * CAP + slot], d = dst[g * CAP + slot];
    int rep = min(s, d), oth = max(s, d);
    g_nscore[rep] = g_escore[g * CAP + slot];
    if (s != d) {
        g_cluster[oth] = rep;
        g_nvalid[oth] = 0;
    }
}

// ----------------------------- pooling of features ----------------------------
__global__ void k_poolA(int F) {
    int tid = blockIdx.x * blockDim.x + threadIdx.x;
    if (tid >= NN * F) return;
    int i = tid / F;
    g_X[tid] = g_nvalid[i] ? g_C[tid] : 0.f;
}

__global__ void k_poolB(int inA, int F) {
    const int* src = inA ? g_srcA : g_srcB;
    const int* dst = inA ? g_dstA : g_dstB;
    const int* cnt = inA ? g_cntA : g_cntB;
    int gt = blockIdx.x * blockDim.x + threadIdx.x;
    int warp = gt >> 5, lane = gt & 31;
    int nw = (gridDim.x * blockDim.x) >> 5;
    for (int rg = warp; rg < NGR * CAP; rg += nw) {
        int g = rg >> CAPB, r = rg & (CAP - 1);
        if (r >= cnt[g] || !g_echosen[rg]) continue;
        int slot = g_eorder[rg];
        int s = src[g * CAP + slot], d = dst[g * CAP + slot];
        if (s == d) continue;
        int rep = min(s, d), oth = max(s, d);
        const float* co = &g_C[oth * F];
        float* xr = &g_X[rep * F];
        for (int f = lane; f < F; f += 32) atomicAdd(&xr[f], co[f]);
    }
}

__global__ void k_poolC(int F) {
    int tid = blockIdx.x * blockDim.x + threadIdx.x;
    if (tid >= NN * F) return;
    int i = tid / F;
    g_X[tid] = fmaxf(g_X[tid] * g_nscore[i], 0.f);   // scale + relu
}

// ----------------------------- coalesce edges to next level -------------------
__global__ void __launch_bounds__(SORT_T, 1) k_coalesce(int inA) {
    extern __shared__ char smraw[];
    int g = blockIdx.x, base = g * CAP, t = threadIdx.x;
    const int* src = inA ? g_srcA : g_srcB;
    const int* dst = inA ? g_dstA : g_dstB;
    const int* cntp = inA ? g_cntA : g_cntB;
    int* osrc = inA ? g_srcB : g_srcA;
    int* odst = inA ? g_dstB : g_dstA;
    int* ocnt = inA ? g_cntB : g_cntA;
    int cnt = cntp[g]; if (cnt > CAP) cnt = CAP;

    unsigned long long keys[SORT_I];
#pragma unroll
    for (int i = 0; i < SORT_I; i++) {
        int slot = t * SORT_I + i;
        if (slot < cnt) {
            int ns = g_cluster[src[base + slot]] & (PER - 1);
            int nd = g_cluster[dst[base + slot]] & (PER - 1);
            keys[i] = ((unsigned long long)(unsigned)((ns << 9) | nd) << CAPB) | (unsigned)slot;
        } else keys[i] = (1ull << 32);   // pad: pair-field = 2^18, sorts last
    }
    {
        typename SortT64::TempStorage& temp =
            *reinterpret_cast<typename SortT64::TempStorage*>(smraw);
        SortT64(temp).Sort(keys, CAPB, 33);
    }
    __syncthreads();
    unsigned long long* lastk = (unsigned long long*)smraw;          // SORT_T
    int* scan = (int*)(smraw + SORT_T * sizeof(unsigned long long)); // SORT_T
    lastk[t] = keys[SORT_I - 1];
    __syncthreads();
    unsigned prevl = (t == 0) ? 0xFFFFFFFFu : (unsigned)(lastk[t - 1] >> CAPB);
    int flags[SORT_I]; int cl = 0;
#pragma unroll
    for (int i = 0; i < SORT_I; i++) {
        int r = t * SORT_I + i;
        unsigned lk = (unsigned)(keys[i] >> CAPB);
        bool f = (r < cnt) && (lk != prevl);
        flags[i] = f; cl += f; prevl = lk;
    }
    __syncthreads();
    scan[t] = cl;
    __syncthreads();
    for (int off = 1; off < SORT_T; off <<= 1) {
        int v = (t >= off) ? scan[t - off] : 0;
        __syncthreads();
        scan[t] += v;
        __syncthreads();
    }
    int pos = scan[t] - cl;
#pragma unroll
    for (int i = 0; i < SORT_I; i++) {
        if (flags[i]) {
            unsigned lk = (unsigned)(keys[i] >> CAPB);
            osrc[base + pos] = g * PER + ((lk >> 9) & 511);
            odst[base + pos] = g * PER + (lk & 511);
            g_eidx[base + pos] = pos;
            pos++;
        }
    }
    if (t == SORT_T - 1) ocnt[g] = scan[t];
}

// ----------------------------- GEMM (g_B = A @ W), f32x2 FFMA2 -----------------
__global__ void k_gemm(const float* __restrict__ Ax, int K, int Nc, const float* __restrict__ W) {
    const float* A = Ax ? Ax : g_X;
    __shared__ float As[64][17];
    __shared__ float Bs[16][66];     // 66: keeps f32x2 pairs 8B-aligned per row
    int t = threadIdx.x;
    int bm = blockIdx.y * 64, bn = blockIdx.x * 64;
    int tm = (t >> 4) << 2, tn = (t & 15) << 2;
    unsigned long long acc2[4][2];
#pragma unroll
    for (int i = 0; i < 4; i++) { acc2[i][0] = pack2(0.f, 0.f); acc2[i][1] = pack2(0.f, 0.f); }

    for (int k0 = 0; k0 < K; k0 += 16) {
#pragma unroll
        for (int i = 0; i < 4; i++) {
            int lin = t + i * 256;
            int m = lin >> 4, kk = lin & 15;
            As[m][kk] = (k0 + kk < K) ? A[(bm + m) * K + k0 + kk] : 0.f;
            int k2 = lin >> 6, n2 = lin & 63;
            Bs[k2][n2] = (k0 + k2 < K && bn + n2 < Nc) ? W[(k0 + k2) * Nc + bn + n2] : 0.f;
        }
        __syncthreads();
#pragma unroll
        for (int kk = 0; kk < 16; kk++) {
            unsigned long long b0 = *(const unsigned long long*)&Bs[kk][tn];
            unsigned long long b1 = *(const unsigned long long*)&Bs[kk][tn + 2];
#pragma unroll
            for (int i = 0; i < 4; i++) {
                float av = As[tm + i][kk];
                unsigned long long ap = pack2(av, av);
                acc2[i][0] = fma2(ap, b0, acc2[i][0]);
                acc2[i][1] = fma2(ap, b1, acc2[i][1]);
            }
        }
        __syncthreads();
    }
#pragma unroll
    for (int i = 0; i < 4; i++) {
        float v0, v1, v2, v3;
        unpack2(v0, v1, acc2[i][0]);
        unpack2(v2, v3, acc2[i][1]);
        float vv[4] = {v0, v1, v2, v3};
#pragma unroll
        for (int j = 0; j < 4; j++)
            if (bn + tn + j < Nc) g_B[(bm + tm + i) * Nc + bn + tn + j] = vv[j];
    }
}

// ----------------------------- readout ----------------------------------------
__global__ void k_maxpool() {
    int g = blockIdx.x, f = threadIdx.x;
    if (f >= 600) return;
    float m = -FLT_MAX;
    for (int p = 0; p < PER; p++) {
        int i = g * PER + p;
        if (g_nvalid[i]) m = fmaxf(m, g_X[i * 600 + f]);
    }
    g_pool[g * 600 + f] = m;
}

__global__ void k_mlp(const float* __restrict__ L1w, const float* __restrict__ L1b,
                      const float* __restrict__ L2w, const float* __restrict__ L2b,
                      const float* __restrict__ L3w, const float* __restrict__ L3b,
                      float* __restrict__ out) {
    __shared__ float z1[200];
    __shared__ float z2[20];
    __shared__ float z3[4];
    int g = blockIdx.x, t = threadIdx.x;
    if (t < 200) {
        float a = L1b[t];
        for (int k = 0; k < 600; k++) a += g_pool[g * 600 + k] * L1w[k * 200 + t];
        z1[t] = fmaxf(a, 0.f);
    }
    __syncthreads();
    if (t < 20) {
        float a = L2b[t];
        for (int k = 0; k < 200; k++) a += z1[k] * L2w[k * 20 + t];
        z2[t] = fmaxf(a, 0.f);
    }
    __syncthreads();
    if (t < 4) {
        float a = L3b[t];
        for (int k = 0; k < 20; k++) a += z2[k] * L3w[k * 4 + t];
        z3[t] = fmaxf(a, 0.f);
    }
    __syncthreads();
    if (t == 0) {
        float m = fmaxf(fmaxf(z3[0], z3[1]), fmaxf(z3[2], z3[3]));
        float e0 = expf(z3[0] - m), e1 = expf(z3[1] - m);
        float e2 = expf(z3[2] - m), e3 = expf(z3[3] - m);
        float s = e0 + e1 + e2 + e3;
        out[g * 4 + 0] = e0 / s;
        out[g * 4 + 1] = e1 / s;
        out[g * 4 + 2] = e2 / s;
        out[g * 4 + 3] = e3 / s;
    }
}

// ----------------------------- host orchestration ------------------------------
static void run_level(const float* X, int Fin, int Fout,
                      const float* W, const float* b,
                      const float* Pw, const float* Pb, int inA) {
    const size_t SMEM64 = sizeof(typename SortT64::TempStorage);
    size_t SMEM_DST = sizeof(typename SortT32::TempStorage);
    if (SMEM_DST < (size_t)CAP * 2) SMEM_DST = (size_t)CAP * 2;
    int nch = (Fout + 31) / 32;

    dim3 gg((Fout + 63) / 64, NN / 64);
    k_gemm<<<gg, 256>>>(X, Fin, Fout, W);
    k_node_init<<<64, 256>>>();
    k_sortdst<<<NGR, SORT_T, SMEM_DST>>>(inA);
    k_degself<<<64, 256>>>();
    k_cinit<<<(NN * Fout + 255) / 256, 256>>>(b, Fout);
    k_aggcsr<<<dim3(nch, NGR), 256>>>(Fout);
    k_nodedot<<<(NN * 32) / 256, 256>>>(Pw, Fout);
    k_maxden<<<64, 256>>>(Pb);
    k_sort_score<<<NGR, SORT_T, SMEM64>>>(inA);
    k_match<<<NGR, SORT_T, CAP * 4 + PER>>>(inA);
    k_apply<<<(NGR * CAP) / 256, 256>>>(inA);
    k_poolA<<<(NN * Fout + 255) / 256, 256>>>(Fout);
    k_poolB<<<2048, 256>>>(inA, Fout);
    k_poolC<<<(NN * Fout + 255) / 256, 256>>>(Fout);
    k_coalesce<<<NGR, SORT_T, SMEM64>>>(inA);
}

extern "C" void kernel_launch(void* const* d_in, const int* in_sizes, int n_in,
                              void* d_out, int out_size) {
    (void)in_sizes; (void)n_in; (void)out_size;
    const float* x   = (const float*)d_in[0];
    const int*   ei  = (const int*)d_in[1];
    const float* W1  = (const float*)d_in[3];
    const float* b1  = (const float*)d_in[4];
    const float* W2  = (const float*)d_in[5];
    const float* b2  = (const float*)d_in[6];
    const float* W3  = (const float*)d_in[7];
    const float* b3  = (const float*)d_in[8];
    const float* P1w = (const float*)d_in[9];
    const float* P1b = (const float*)d_in[10];
    const float* P2w = (const float*)d_in[11];
    const float* P2b = (const float*)d_in[12];
    const float* P3w = (const float*)d_in[13];
    const float* P3b = (const float*)d_in[14];
    const float* L1w = (const float*)d_in[15];
    const float* L1b = (const float*)d_in[16];
    const float* L2w = (const float*)d_in[17];
    const float* L2b = (const float*)d_in[18];
    const float* L3w = (const float*)d_in[19];
    const float* L3b = (const float*)d_in[20];
    float* out = (float*)d_out;

    const size_t SMEM64 = sizeof(typename SortT64::TempStorage);
    size_t SMEM_DST = sizeof(typename SortT32::TempStorage);
    if (SMEM_DST < (size_t)CAP * 2) SMEM_DST = (size_t)CAP * 2;
    cudaFuncSetAttribute(k_sort_score, cudaFuncAttributeMaxDynamicSharedMemorySize, (int)SMEM64);
    cudaFuncSetAttribute(k_coalesce,   cudaFuncAttributeMaxDynamicSharedMemorySize, (int)SMEM64);
    cudaFuncSetAttribute(k_sortdst,    cudaFuncAttributeMaxDynamicSharedMemorySize, (int)SMEM_DST);
    cudaFuncSetAttribute(k_match,      cudaFuncAttributeMaxDynamicSharedMemorySize, CAP * 4 + PER);

    k_init0<<<64, 256>>>();
    k_ingest<<<EE / 256, 256>>>(ei);

    run_level(x,       107, 200, W1, b1, P1w, P1b, 1);  // edges A -> B
    run_level(nullptr, 200, 400, W2, b2, P2w, P2b, 0);  // edges B -> A
    run_level(nullptr, 400, 600, W3, b3, P3w, P3b, 1);  // edges A -> B

    k_maxpool<<<NGR, 600>>>();
    k_mlp<<<NGR, 256>>>(L1w, L1b, L2w, L2b, L3w, L3b, out);
}

// round 5
// speedup vs baseline: 1.3315x; 1.1085x over previous
#include <cuda_runtime.h>
#include <cuda_bf16.h>
#include <math.h>
#include <float.h>
#include <cub/block/block_radix_sort.cuh>

#define NN   16384
#define PER  512
#define NGR  32
#define EE   262144
#define CAP  16384      // per-graph edge capacity (2^14)
#define CAPB 14
#define FMAX 600

// ----------------------------- scratch (device globals) -----------------------
__device__ float g_X[NN * FMAX];   // level input features / pooled output
__device__ float g_B[NN * FMAX];   // h = X @ W
__device__ float g_C[NN * FMAX];   // conv output
__device__ float g_na[NN], g_nb[NN];
__device__ float g_dinv[NN], g_cself[NN];
__device__ int   g_cluster[NN];
__device__ int   g_partner[NN];
__device__ float g_nscore[NN];
__device__ unsigned char g_nvalid[NN];
__device__ int   g_rs[NN], g_re[NN];        // CSR row range in dst-sorted order

__device__ int g_srcA[NGR * CAP], g_dstA[NGR * CAP];
__device__ int g_srcB[NGR * CAP], g_dstB[NGR * CAP];
__device__ int g_cntA[NGR], g_cntB[NGR];
__device__ int g_eidx[NGR * CAP];           // stable-tie index (orig order), by slot
__device__ int g_sslot[NGR * CAP];          // dst-sorted rank -> slot
__device__ int g_ssrc[NGR * CAP];           // dst-sorted rank -> global src node
__device__ float g_eex[NGR * CAP];          // by dst-sorted rank
__device__ float g_escore[NGR * CAP];       // by slot
__device__ unsigned long long g_ukey[NGR * CAP];  // by slot: (score desc, idx asc) total order
__device__ float g_pool[NGR * FMAX];

// ----------------------------- helpers ---------------------------------------
__device__ __forceinline__ unsigned enc_f(float f) {
    unsigned u = __float_as_uint(f);
    return (u & 0x80000000u) ? ~u : (u | 0x80000000u);
}

__device__ __forceinline__ unsigned long long pack2(float x, float y) {
    unsigned long long r;
    asm("mov.b64 %0, {%1, %2};" : "=l"(r) : "f"(x), "f"(y));
    return r;
}
__device__ __forceinline__ void unpack2(float& x, float& y, unsigned long long v) {
    asm("mov.b64 {%0, %1}, %2;" : "=f"(x), "=f"(y) : "l"(v));
}
__device__ __forceinline__ unsigned long long fma2(unsigned long long a,
                                                   unsigned long long b,
                                                   unsigned long long c) {
    unsigned long long d;
    asm("fma.rn.f32x2 %0, %1, %2, %3;" : "=l"(d) : "l"(a), "l"(b), "l"(c));
    return d;
}

// ----------------------------- init / ingest ----------------------------------
__global__ void k_init0() {
    int i = blockIdx.x * blockDim.x + threadIdx.x;
    if (i < NN) g_nvalid[i] = 1;
    if (i < NGR) g_cntA[i] = 0;
}

__global__ void k_ingest(const int* __restrict__ ei) {
    int e = blockIdx.x * blockDim.x + threadIdx.x;
    if (e >= EE) return;
    int s = ei[e], d = ei[EE + e];
    int g = s >> 9;
    int pos = atomicAdd(&g_cntA[g], 1);
    if (pos < CAP) {
        g_srcA[g * CAP + pos] = s;
        g_dstA[g * CAP + pos] = d;
        g_eidx[g * CAP + pos] = e;
    }
}

// ----------------------------- dst-sort + CSR + node init (per-graph CTA) ------
constexpr int SORT_T = 512;
constexpr int SORT_I = 32;
using SortT64 = cub::BlockRadixSort<unsigned long long, SORT_T, SORT_I>;
using SortT32 = cub::BlockRadixSort<unsigned, SORT_T, SORT_I>;

__global__ void __launch_bounds__(SORT_T, 1) k_sortdst(int inA) {
    extern __shared__ char smraw[];
    const int* src = inA ? g_srcA : g_srcB;
    const int* dst = inA ? g_dstA : g_dstB;
    const int* cntp = inA ? g_cntA : g_cntB;
    int g = blockIdx.x, base = g * CAP, t = threadIdx.x;
    int cnt = cntp[g]; if (cnt > CAP) cnt = CAP;

    unsigned keys[SORT_I];
#pragma unroll
    for (int i = 0; i < SORT_I; i++) {
        int slot = t * SORT_I + i;
        if (slot < cnt) {
            unsigned d = (unsigned)(dst[base + slot] & (PER - 1));
            keys[i] = (d << CAPB) | (unsigned)slot;
        } else {
            keys[i] = (512u << CAPB) | (unsigned)slot;   // pad sorts after all real d
        }
    }
    {
        typename SortT32::TempStorage& temp =
            *reinterpret_cast<typename SortT32::TempStorage*>(smraw);
        SortT32(temp).Sort(keys, CAPB, 24);
    }
    __syncthreads();
    unsigned short* d16 = (unsigned short*)smraw;   // reuse smem: CAP u16
#pragma unroll
    for (int i = 0; i < SORT_I; i++) {
        int r = t * SORT_I + i;
        unsigned k = keys[i];
        int slot = (int)(k & (CAP - 1));
        int d = (int)(k >> CAPB);
        if (r < cnt) {
            g_sslot[base + r] = slot;
            g_ssrc[base + r] = src[base + slot];
            d16[r] = (unsigned short)d;
        }
    }
    __syncthreads();
    if (t < PER) { g_rs[g * PER + t] = 0; g_re[g * PER + t] = 0; }
    __syncthreads();
    for (int r = t; r < cnt; r += SORT_T) {
        int d = d16[r];
        if (r == 0 || d16[r - 1] != d) g_rs[g * PER + d] = r;
        if (r == cnt - 1 || d16[r + 1] != d) g_re[g * PER + d] = r + 1;
    }
    __syncthreads();
    // node init: degree/self-loop/norm + per-level resets (t < PER == SORT_T)
    {
        int nid = g * PER + t;
        int rs = g_rs[nid], re = g_re[nid];
        int selfv = 0;
        for (int r = rs; r < re; r++)
            if (g_ssrc[base + r] == nid) selfv = 1;
        float add = selfv ? 0.f : 1.f;
        float td = (float)(re - rs) + add;
        g_dinv[nid] = rsqrtf(td);
        g_cself[nid] = add / td;
        g_cluster[nid] = nid;
        g_nscore[nid] = 1.f;
        g_partner[nid] = -1;
    }
}

// CSR aggregation fused with cinit: C = cself*B + bias + dinv[d]*sum(dinv[s]*B[s])
__global__ void k_aggcsr(int F, const float* __restrict__ bias) {
    int g = blockIdx.y;
    int f = blockIdx.x * 32 + (threadIdx.x & 31);
    int w = threadIdx.x >> 5;
    bool fv = (f < F);
    int base = g * CAP;
    float bf = fv ? bias[f] : 0.f;
    for (int d = w; d < PER; d += 8) {
        int nid = g * PER + d;
        int rs = g_rs[nid], re = g_re[nid];
        float acc = 0.f;
        for (int r = rs; r < re; r++) {
            int s = g_ssrc[base + r];
            float v = fv ? g_B[s * F + f] : 0.f;
            acc += g_dinv[s] * v;
        }
        if (fv)
            g_C[nid * F + f] = g_cself[nid] * g_B[nid * F + f] + bf + acc * g_dinv[nid];
    }
}

__global__ void k_nodedot(const float* __restrict__ Pw, int F) {
    int gt = blockIdx.x * blockDim.x + threadIdx.x;
    int node = gt >> 5, lane = gt & 31;
    if (node >= NN) return;
    const float* c = &g_C[node * F];
    float a = 0.f, b = 0.f;
    for (int f = lane; f < F; f += 32) {
        float v = c[f];
        a += v * Pw[f];
        b += v * Pw[F + f];
    }
    for (int o = 16; o > 0; o >>= 1) {
        a += __shfl_down_sync(0xFFFFFFFFu, a, o);
        b += __shfl_down_sync(0xFFFFFFFFu, b, o);
    }
    if (lane == 0) { g_na[node] = a; g_nb[node] = b; }
}

// per-dst softmax (max, den, score, total-order key) — deterministic, no atomics
__global__ void k_maxden(const float* __restrict__ Pb) {
    int nid = blockIdx.x * blockDim.x + threadIdx.x;
    if (nid >= NN) return;
    int g = nid >> 9, base = g * CAP;
    int rs = g_rs[nid], re = g_re[nid];
    if (rs >= re) return;
    float nbd = g_nb[nid] + Pb[0];
    float mx = -FLT_MAX;
    for (int r = rs; r < re; r++)
        mx = fmaxf(mx, g_na[g_ssrc[base + r]] + nbd);
    float den = 0.f;
    for (int r = rs; r < re; r++) {
        float ex = expf(g_na[g_ssrc[base + r]] + nbd - mx);
        g_eex[base + r] = ex;
        den += ex;
    }
    den = fmaxf(den, 1e-16f);
    for (int r = rs; r < re; r++) {
        float sc = g_eex[base + r] / den + 0.1f;
        int slot = g_sslot[base + r];
        g_escore[base + slot] = sc;
        // bigger key = better: score desc, then smaller original index
        g_ukey[base + slot] = ((unsigned long long)enc_f(sc) << 18)
                            | (unsigned)(0x3FFFFu - (unsigned)g_eidx[base + slot]);
    }
}

// ----------------------------- locally-dominant greedy matching ----------------
// Equivalent to sequential greedy over (score desc, idx asc): an edge is chosen
// iff its unique key is the max among alive edges at BOTH endpoints; iterate.
__global__ void __launch_bounds__(SORT_T, 1) k_matchdom(int inA) {
    extern __shared__ char sm[];
    unsigned long long* ek   = (unsigned long long*)sm;                       // CAP
    unsigned long long* best = (unsigned long long*)(sm + (size_t)CAP * 8);   // PER
    unsigned* pairs = (unsigned*)(sm + (size_t)CAP * 8 + PER * 8);            // CAP
    unsigned char* marked = (unsigned char*)(sm + (size_t)CAP * 8 + PER * 8 + (size_t)CAP * 4); // PER
    int* sflag = (int*)(sm + (size_t)CAP * 8 + PER * 8 + (size_t)CAP * 4 + PER);
    const int* src = inA ? g_srcA : g_srcB;
    const int* dst = inA ? g_dstA : g_dstB;
    const int* cntp = inA ? g_cntA : g_cntB;
    int g = blockIdx.x, base = g * CAP, t = threadIdx.x;
    int cnt = cntp[g]; if (cnt > CAP) cnt = CAP;

    for (int sl = t; sl < cnt; sl += SORT_T) {
        int s = src[base + sl] & (PER - 1);
        int d = dst[base + sl] & (PER - 1);
        pairs[sl] = (unsigned)((s << 9) | d);
        ek[sl] = g_ukey[base + sl];
    }
    for (int p = t; p < PER; p += SORT_T)
        marked[p] = g_nvalid[g * PER + p] ? 0 : 1;
    __syncthreads();

    while (true) {
        for (int p = t; p < PER; p += SORT_T) best[p] = 0ull;
        if (t == 0) *sflag = 0;
        __syncthreads();
        bool any = false;
        for (int sl = t; sl < cnt; sl += SORT_T) {
            unsigned pr = pairs[sl];
            if (pr == 0xFFFFFFFFu) continue;
            int s = pr >> 9, d = pr & 511;
            if (marked[s] | marked[d]) { pairs[sl] = 0xFFFFFFFFu; continue; }
            any = true;
            unsigned long long k = ek[sl];
            atomicMax(&best[s], k);
            if (d != s) atomicMax(&best[d], k);
        }
        if (any) *sflag = 1;
        __syncthreads();
        if (!*sflag) break;
        for (int sl = t; sl < cnt; sl += SORT_T) {
            unsigned pr = pairs[sl];
            if (pr == 0xFFFFFFFFu) continue;
            int s = pr >> 9, d = pr & 511;
            unsigned long long k = ek[sl];
            if (best[s] == k && best[d] == k) {      // dominant at both ends -> chosen
                marked[s] = 1; marked[d] = 1;
                pairs[sl] = 0xFFFFFFFFu;
                int sG = src[base + sl], dG = dst[base + sl];
                int rep = min(sG, dG), oth = max(sG, dG);
                g_nscore[rep] = g_escore[base + sl];
                if (sG != dG) {
                    g_cluster[oth] = rep;
                    g_nvalid[oth] = 0;
                    g_partner[rep] = oth;
                }
            }
        }
        __syncthreads();
    }
}

// ----------------------------- fused pooling (no atomics) ----------------------
__global__ void k_pool(int F) {
    int tid = blockIdx.x * blockDim.x + threadIdx.x;
    if (tid >= NN * F) return;
    int i = tid / F, f = tid - i * F;
    float v = 0.f;
    if (g_nvalid[i]) {
        v = g_C[tid];
        int p = g_partner[i];
        if (p >= 0) v += g_C[p * F + f];
        v = fmaxf(v * g_nscore[i], 0.f);
    }
    g_X[tid] = v;
}

// ----------------------------- coalesce edges to next level -------------------
__global__ void __launch_bounds__(SORT_T, 1) k_coalesce(int inA) {
    extern __shared__ char smraw[];
    int g = blockIdx.x, base = g * CAP, t = threadIdx.x;
    const int* src = inA ? g_srcA : g_srcB;
    const int* dst = inA ? g_dstA : g_dstB;
    const int* cntp = inA ? g_cntA : g_cntB;
    int* osrc = inA ? g_srcB : g_srcA;
    int* odst = inA ? g_dstB : g_dstA;
    int* ocnt = inA ? g_cntB : g_cntA;
    int cnt = cntp[g]; if (cnt > CAP) cnt = CAP;

    unsigned long long keys[SORT_I];
#pragma unroll
    for (int i = 0; i < SORT_I; i++) {
        int slot = t * SORT_I + i;
        if (slot < cnt) {
            int ns = g_cluster[src[base + slot]] & (PER - 1);
            int nd = g_cluster[dst[base + slot]] & (PER - 1);
            keys[i] = ((unsigned long long)(unsigned)((ns << 9) | nd) << CAPB) | (unsigned)slot;
        } else keys[i] = (1ull << 32);   // pad: pair-field = 2^18, sorts last
    }
    {
        typename SortT64::TempStorage& temp =
            *reinterpret_cast<typename SortT64::TempStorage*>(smraw);
        SortT64(temp).Sort(keys, CAPB, 33);
    }
    __syncthreads();
    unsigned long long* lastk = (unsigned long long*)smraw;          // SORT_T
    int* scan = (int*)(smraw + SORT_T * sizeof(unsigned long long)); // SORT_T
    lastk[t] = keys[SORT_I - 1];
    __syncthreads();
    unsigned prevl = (t == 0) ? 0xFFFFFFFFu : (unsigned)(lastk[t - 1] >> CAPB);
    int flags[SORT_I]; int cl = 0;
#pragma unroll
    for (int i = 0; i < SORT_I; i++) {
        int r = t * SORT_I + i;
        unsigned lk = (unsigned)(keys[i] >> CAPB);
        bool f = (r < cnt) && (lk != prevl);
        flags[i] = f; cl += f; prevl = lk;
    }
    __syncthreads();
    scan[t] = cl;
    __syncthreads();
    for (int off = 1; off < SORT_T; off <<= 1) {
        int v = (t >= off) ? scan[t - off] : 0;
        __syncthreads();
        scan[t] += v;
        __syncthreads();
    }
    int pos = scan[t] - cl;
#pragma unroll
    for (int i = 0; i < SORT_I; i++) {
        if (flags[i]) {
            unsigned lk = (unsigned)(keys[i] >> CAPB);
            osrc[base + pos] = g * PER + ((lk >> 9) & 511);
            odst[base + pos] = g * PER + (lk & 511);
            g_eidx[base + pos] = pos;
            pos++;
        }
    }
    if (t == SORT_T - 1) ocnt[g] = scan[t];
}

// ----------------------------- GEMM (g_B = A @ W), f32x2 FFMA2 -----------------
__global__ void k_gemm(const float* __restrict__ Ax, int K, int Nc, const float* __restrict__ W) {
    const float* A = Ax ? Ax : g_X;
    __shared__ float As[64][17];
    __shared__ float Bs[16][66];     // 66: keeps f32x2 pairs 8B-aligned per row
    int t = threadIdx.x;
    int bm = blockIdx.y * 64, bn = blockIdx.x * 64;
    int tm = (t >> 4) << 2, tn = (t & 15) << 2;
    unsigned long long acc2[4][2];
#pragma unroll
    for (int i = 0; i < 4; i++) { acc2[i][0] = pack2(0.f, 0.f); acc2[i][1] = pack2(0.f, 0.f); }

    for (int k0 = 0; k0 < K; k0 += 16) {
#pragma unroll
        for (int i = 0; i < 4; i++) {
            int lin = t + i * 256;
            int m = lin >> 4, kk = lin & 15;
            As[m][kk] = (k0 + kk < K) ? A[(bm + m) * K + k0 + kk] : 0.f;
            int k2 = lin >> 6, n2 = lin & 63;
            Bs[k2][n2] = (k0 + k2 < K && bn + n2 < Nc) ? W[(k0 + k2) * Nc + bn + n2] : 0.f;
        }
        __syncthreads();
#pragma unroll
        for (int kk = 0; kk < 16; kk++) {
            unsigned long long b0 = *(const unsigned long long*)&Bs[kk][tn];
            unsigned long long b1 = *(const unsigned long long*)&Bs[kk][tn + 2];
#pragma unroll
            for (int i = 0; i < 4; i++) {
                float av = As[tm + i][kk];
                unsigned long long ap = pack2(av, av);
                acc2[i][0] = fma2(ap, b0, acc2[i][0]);
                acc2[i][1] = fma2(ap, b1, acc2[i][1]);
            }
        }
        __syncthreads();
    }
#pragma unroll
    for (int i = 0; i < 4; i++) {
        float v0, v1, v2, v3;
        unpack2(v0, v1, acc2[i][0]);
        unpack2(v2, v3, acc2[i][1]);
        float vv[4] = {v0, v1, v2, v3};
#pragma unroll
        for (int j = 0; j < 4; j++)
            if (bn + tn + j < Nc) g_B[(bm + tm + i) * Nc + bn + tn + j] = vv[j];
    }
}

// ----------------------------- readout ----------------------------------------
__global__ void k_maxpool() {
    int g = blockIdx.y;
    int f = blockIdx.x * 128 + threadIdx.x;
    if (f >= 600) return;
    float m = -FLT_MAX;
    for (int p = 0; p < PER; p++) {
        int i = g * PER + p;
        if (g_nvalid[i]) m = fmaxf(m, g_X[i * 600 + f]);
    }
    g_pool[g * 600 + f] = m;
}

__global__ void k_mlp(const float* __restrict__ L1w, const float* __restrict__ L1b,
                      const float* __restrict__ L2w, const float* __restrict__ L2b,
                      const float* __restrict__ L3w, const float* __restrict__ L3b,
                      float* __restrict__ out) {
    __shared__ float z1[200];
    __shared__ float z2[20];
    __shared__ float z3[4];
    int g = blockIdx.x, t = threadIdx.x;
    if (t < 200) {
        float a = L1b[t];
        for (int k = 0; k < 600; k++) a += g_pool[g * 600 + k] * L1w[k * 200 + t];
        z1[t] = fmaxf(a, 0.f);
    }
    __syncthreads();
    if (t < 20) {
        float a = L2b[t];
        for (int k = 0; k < 200; k++) a += z1[k] * L2w[k * 20 + t];
        z2[t] = fmaxf(a, 0.f);
    }
    __syncthreads();
    if (t < 4) {
        float a = L3b[t];
        for (int k = 0; k < 20; k++) a += z2[k] * L3w[k * 4 + t];
        z3[t] = fmaxf(a, 0.f);
    }
    __syncthreads();
    if (t == 0) {
        float m = fmaxf(fmaxf(z3[0], z3[1]), fmaxf(z3[2], z3[3]));
        float e0 = expf(z3[0] - m), e1 = expf(z3[1] - m);
        float e2 = expf(z3[2] - m), e3 = expf(z3[3] - m);
        float s = e0 + e1 + e2 + e3;
        out[g * 4 + 0] = e0 / s;
        out[g * 4 + 1] = e1 / s;
        out[g * 4 + 2] = e2 / s;
        out[g * 4 + 3] = e3 / s;
    }
}

// ----------------------------- host orchestration ------------------------------
static const size_t MATCH_SMEM = (size_t)CAP * 8 + PER * 8 + (size_t)CAP * 4 + PER + 16;

static void run_level(const float* X, int Fin, int Fout,
                      const float* W, const float* b,
                      const float* Pw, const float* Pb, int inA) {
    const size_t SMEM64 = sizeof(typename SortT64::TempStorage);
    size_t SMEM_DST = sizeof(typename SortT32::TempStorage);
    if (SMEM_DST < (size_t)CAP * 2) SMEM_DST = (size_t)CAP * 2;
    int nch = (Fout + 31) / 32;

    dim3 gg((Fout + 63) / 64, NN / 64);
    k_gemm<<<gg, 256>>>(X, Fin, Fout, W);
    k_sortdst<<<NGR, SORT_T, SMEM_DST>>>(inA);
    k_aggcsr<<<dim3(nch, NGR), 256>>>(Fout, b);
    k_nodedot<<<(NN * 32) / 256, 256>>>(Pw, Fout);
    k_maxden<<<64, 256>>>(Pb);
    k_matchdom<<<NGR, SORT_T, MATCH_SMEM>>>(inA);
    k_pool<<<(NN * Fout + 255) / 256, 256>>>(Fout);
    k_coalesce<<<NGR, SORT_T, SMEM64>>>(inA);
}

extern "C" void kernel_launch(void* const* d_in, const int* in_sizes, int n_in,
                              void* d_out, int out_size) {
    (void)in_sizes; (void)n_in; (void)out_size;
    const float* x   = (const float*)d_in[0];
    const int*   ei  = (const int*)d_in[1];
    const float* W1  = (const float*)d_in[3];
    const float* b1  = (const float*)d_in[4];
    const float* W2  = (const float*)d_in[5];
    const float* b2  = (const float*)d_in[6];
    const float* W3  = (const float*)d_in[7];
    const float* b3  = (const float*)d_in[8];
    const float* P1w = (const float*)d_in[9];
    const float* P1b = (const float*)d_in[10];
    const float* P2w = (const float*)d_in[11];
    const float* P2b = (const float*)d_in[12];
    const float* P3w = (const float*)d_in[13];
    const float* P3b = (const float*)d_in[14];
    const float* L1w = (const float*)d_in[15];
    const float* L1b = (const float*)d_in[16];
    const float* L2w = (const float*)d_in[17];
    const float* L2b = (const float*)d_in[18];
    const float* L3w = (const float*)d_in[19];
    const float* L3b = (const float*)d_in[20];
    float* out = (float*)d_out;

    const size_t SMEM64 = sizeof(typename SortT64::TempStorage);
    size_t SMEM_DST = sizeof(typename SortT32::TempStorage);
    if (SMEM_DST < (size_t)CAP * 2) SMEM_DST = (size_t)CAP * 2;
    cudaFuncSetAttribute(k_coalesce, cudaFuncAttributeMaxDynamicSharedMemorySize, (int)SMEM64);
    cudaFuncSetAttribute(k_sortdst,  cudaFuncAttributeMaxDynamicSharedMemorySize, (int)SMEM_DST);
    cudaFuncSetAttribute(k_matchdom, cudaFuncAttributeMaxDynamicSharedMemorySize, (int)MATCH_SMEM);

    k_init0<<<64, 256>>>();
    k_ingest<<<EE / 256, 256>>>(ei);

    run_level(x,       107, 200, W1, b1, P1w, P1b, 1);  // edges A -> B
    run_level(nullptr, 200, 400, W2, b2, P2w, P2b, 0);  // edges B -> A
    run_level(nullptr, 400, 600, W3, b3, P3w, P3b, 1);  // edges A -> B

    k_maxpool<<<dim3(5, NGR), 128>>>();
    k_mlp<<<NGR, 256>>>(L1w, L1b, L2w, L2b, L3w, L3b, out);
}

// round 6
// speedup vs baseline: 1.7098x; 1.2841x over previous
#include <cuda_runtime.h>
#include <cuda_bf16.h>
#include <math.h>
#include <float.h>
#include <cub/block/block_radix_sort.cuh>

#define NN   16384
#define PER  512
#define NGR  32
#define EE   262144
#define CAP  16384      // per-graph edge capacity (2^14)
#define CAPB 14
#define FMAX 600

// ----------------------------- scratch (device globals) -----------------------
__device__ float g_X[NN * FMAX];   // level input features / pooled output
__device__ float g_B[NN * FMAX];   // h = X @ W
__device__ float g_C[NN * FMAX];   // conv output
__device__ float g_na[NN], g_nb[NN];
__device__ float g_dinv[NN], g_cself[NN];
__device__ int   g_cluster[NN];
__device__ int   g_partner[NN];
__device__ float g_nscore[NN];
__device__ unsigned char g_nvalid[NN];
__device__ int   g_rs[NN], g_re[NN];        // CSR row range in dst-sorted order

__device__ int g_srcA[NGR * CAP], g_dstA[NGR * CAP];
__device__ int g_srcB[NGR * CAP], g_dstB[NGR * CAP];
__device__ int g_cntA[NGR], g_cntB[NGR];
__device__ int g_eidx[NGR * CAP];           // stable-tie index (orig order), by slot
__device__ int g_sslot[NGR * CAP];          // dst-sorted rank -> slot
__device__ int g_ssrc[NGR * CAP];           // dst-sorted rank -> global src node
__device__ float g_escore[NGR * CAP];       // by slot
__device__ unsigned long long g_ukey[NGR * CAP];  // by slot: (score desc, idx asc)
__device__ float g_pool[NGR * FMAX];

// ----------------------------- helpers ---------------------------------------
__device__ __forceinline__ unsigned enc_f(float f) {
    unsigned u = __float_as_uint(f);
    return (u & 0x80000000u) ? ~u : (u | 0x80000000u);
}
__device__ __forceinline__ unsigned long long pack2(float x, float y) {
    unsigned long long r;
    asm("mov.b64 %0, {%1, %2};" : "=l"(r) : "f"(x), "f"(y));
    return r;
}
__device__ __forceinline__ void unpack2(float& x, float& y, unsigned long long v) {
    asm("mov.b64 {%0, %1}, %2;" : "=f"(x), "=f"(y) : "l"(v));
}
__device__ __forceinline__ unsigned long long fma2(unsigned long long a,
                                                   unsigned long long b,
                                                   unsigned long long c) {
    unsigned long long d;
    asm("fma.rn.f32x2 %0, %1, %2, %3;" : "=l"(d) : "l"(a), "l"(b), "l"(c));
    return d;
}

// ----------------------------- init / ingest ----------------------------------
__global__ void k_init0() {
    int i = blockIdx.x * blockDim.x + threadIdx.x;
    if (i < NN) g_nvalid[i] = 1;
    if (i < NGR) g_cntA[i] = 0;
}

__global__ void k_ingest(const int* __restrict__ ei) {
    int e = blockIdx.x * blockDim.x + threadIdx.x;
    if (e >= EE) return;
    int s = ei[e], d = ei[EE + e];
    int g = s >> 9;
    int pos = atomicAdd(&g_cntA[g], 1);
    if (pos < CAP) {
        g_srcA[g * CAP + pos] = s;
        g_dstA[g * CAP + pos] = d;
        g_eidx[g * CAP + pos] = e;
    }
}

// ----------------------------- dst-sort + CSR + node init (per-graph CTA) ------
constexpr int SORT_T = 512;
constexpr int SORT_I = 32;
using SortT64 = cub::BlockRadixSort<unsigned long long, SORT_T, SORT_I>;
using SortT32 = cub::BlockRadixSort<unsigned, SORT_T, SORT_I>;

__global__ void __launch_bounds__(SORT_T, 1) k_sortdst(int inA) {
    extern __shared__ char smraw[];
    const int* src = inA ? g_srcA : g_srcB;
    const int* dst = inA ? g_dstA : g_dstB;
    const int* cntp = inA ? g_cntA : g_cntB;
    int g = blockIdx.x, base = g * CAP, t = threadIdx.x;
    int cnt = cntp[g]; if (cnt > CAP) cnt = CAP;

    unsigned keys[SORT_I];
#pragma unroll
    for (int i = 0; i < SORT_I; i++) {
        int slot = t * SORT_I + i;
        if (slot < cnt) {
            unsigned d = (unsigned)(dst[base + slot] & (PER - 1));
            keys[i] = (d << CAPB) | (unsigned)slot;
        } else {
            keys[i] = (512u << CAPB) | (unsigned)slot;   // pad sorts after all real d
        }
    }
    {
        typename SortT32::TempStorage& temp =
            *reinterpret_cast<typename SortT32::TempStorage*>(smraw);
        SortT32(temp).Sort(keys, CAPB, 24);
    }
    __syncthreads();
    unsigned short* d16 = (unsigned short*)smraw;   // reuse smem: CAP u16
#pragma unroll
    for (int i = 0; i < SORT_I; i++) {
        int r = t * SORT_I + i;
        unsigned k = keys[i];
        int slot = (int)(k & (CAP - 1));
        int d = (int)(k >> CAPB);
        if (r < cnt) {
            g_sslot[base + r] = slot;
            g_ssrc[base + r] = src[base + slot];
            d16[r] = (unsigned short)d;
        }
    }
    __syncthreads();
    if (t < PER) { g_rs[g * PER + t] = 0; g_re[g * PER + t] = 0; }
    __syncthreads();
    for (int r = t; r < cnt; r += SORT_T) {
        int d = d16[r];
        if (r == 0 || d16[r - 1] != d) g_rs[g * PER + d] = r;
        if (r == cnt - 1 || d16[r + 1] != d) g_re[g * PER + d] = r + 1;
    }
    __syncthreads();
    // node init: degree/self-loop/norm + per-level resets (SORT_T == PER)
    {
        int nid = g * PER + t;
        int rs = g_rs[nid], re = g_re[nid];
        int selfv = 0;
        for (int r = rs; r < re; r++)
            if (g_ssrc[base + r] == nid) selfv = 1;
        float add = selfv ? 0.f : 1.f;
        float td = (float)(re - rs) + add;
        g_dinv[nid] = rsqrtf(td);
        g_cself[nid] = add / td;
        g_cluster[nid] = nid;
        g_nscore[nid] = 1.f;
        g_partner[nid] = -1;
    }
}

// CSR aggregation fused with cinit: C = cself*B + bias + dinv[d]*sum(dinv[s]*B[s])
__global__ void k_aggcsr(int F, const float* __restrict__ bias) {
    int g = blockIdx.y;
    int f = blockIdx.x * 32 + (threadIdx.x & 31);
    int w = threadIdx.x >> 5;
    bool fv = (f < F);
    int base = g * CAP;
    float bf = fv ? bias[f] : 0.f;
    for (int d = w; d < PER; d += 8) {
        int nid = g * PER + d;
        int rs = g_rs[nid], re = g_re[nid];
        float acc = 0.f;
        for (int r = rs; r < re; r++) {
            int s = g_ssrc[base + r];
            float v = fv ? g_B[s * F + f] : 0.f;
            acc += g_dinv[s] * v;
        }
        if (fv)
            g_C[nid * F + f] = g_cself[nid] * g_B[nid * F + f] + bf + acc * g_dinv[nid];
    }
}

__global__ void k_nodedot(const float* __restrict__ Pw, int F) {
    int gt = blockIdx.x * blockDim.x + threadIdx.x;
    int node = gt >> 5, lane = gt & 31;
    if (node >= NN) return;
    const float* c = &g_C[node * F];
    float a = 0.f, b = 0.f;
    for (int f = lane; f < F; f += 32) {
        float v = c[f];
        a += v * Pw[f];
        b += v * Pw[F + f];
    }
    for (int o = 16; o > 0; o >>= 1) {
        a += __shfl_down_sync(0xFFFFFFFFu, a, o);
        b += __shfl_down_sync(0xFFFFFFFFu, b, o);
    }
    if (lane == 0) { g_na[node] = a; g_nb[node] = b; }
}

// per-dst softmax: warp per node, shuffle reductions — deterministic
__global__ void k_maxden(const float* __restrict__ Pb) {
    int gt = blockIdx.x * blockDim.x + threadIdx.x;
    int node = gt >> 5, lane = gt & 31;
    if (node >= NN) return;
    int g = node >> 9, base = g * CAP;
    int rs = g_rs[node], re = g_re[node];
    if (rs >= re) return;
    float nbd = g_nb[node] + Pb[0];
    float mx = -FLT_MAX;
    for (int r = rs + lane; r < re; r += 32)
        mx = fmaxf(mx, g_na[g_ssrc[base + r]] + nbd);
    for (int o = 16; o > 0; o >>= 1)
        mx = fmaxf(mx, __shfl_xor_sync(0xFFFFFFFFu, mx, o));
    float den = 0.f;
    for (int r = rs + lane; r < re; r += 32)
        den += expf(g_na[g_ssrc[base + r]] + nbd - mx);
    for (int o = 16; o > 0; o >>= 1)
        den += __shfl_xor_sync(0xFFFFFFFFu, den, o);
    den = fmaxf(den, 1e-16f);
    for (int r = rs + lane; r < re; r += 32) {
        float ex = expf(g_na[g_ssrc[base + r]] + nbd - mx);
        float sc = ex / den + 0.1f;
        int slot = g_sslot[base + r];
        g_escore[base + slot] = sc;
        g_ukey[base + slot] = ((unsigned long long)enc_f(sc) << 18)
                            | (unsigned)(0x3FFFFu - (unsigned)g_eidx[base + slot]);
    }
}

// ----------------------------- locally-dominant greedy matching ----------------
// Equivalent to sequential greedy over (score desc, idx asc). Alive-list
// compaction: only surviving edges are revisited each round.
static const size_t MATCH_SMEM = (size_t)CAP * 4 + PER * 8 + (size_t)CAP * 4 + PER + 32;

__global__ void __launch_bounds__(SORT_T, 1) k_matchdom(int inA) {
    extern __shared__ char sm[];
    unsigned* pairs = (unsigned*)sm;                                        // CAP u32
    unsigned long long* best = (unsigned long long*)(sm + (size_t)CAP * 4); // PER u64
    unsigned short* lst0 = (unsigned short*)(sm + (size_t)CAP * 4 + PER * 8);
    unsigned short* lst1 = lst0 + CAP;
    unsigned char* marked = (unsigned char*)(sm + (size_t)CAP * 4 + PER * 8 + (size_t)CAP * 4);
    int* cntr = (int*)(sm + (size_t)CAP * 4 + PER * 8 + (size_t)CAP * 4 + PER);
    const int* src = inA ? g_srcA : g_srcB;
    const int* dst = inA ? g_dstA : g_dstB;
    const int* cntp = inA ? g_cntA : g_cntB;
    int g = blockIdx.x, base = g * CAP, t = threadIdx.x;
    int cnt = cntp[g]; if (cnt > CAP) cnt = CAP;

    for (int sl = t; sl < cnt; sl += SORT_T) {
        int s = src[base + sl] & (PER - 1);
        int d = dst[base + sl] & (PER - 1);
        pairs[sl] = (unsigned)((s << 9) | d);
        lst0[sl] = (unsigned short)sl;
    }
    for (int p = t; p < PER; p += SORT_T)
        marked[p] = g_nvalid[g * PER + p] ? 0 : 1;
    __syncthreads();

    unsigned short* cur = lst0;
    unsigned short* nxt = lst1;
    int n = cnt;
    while (true) {
        for (int p = t; p < PER; p += SORT_T) best[p] = 0ull;
        if (t == 0) cntr[0] = 0;
        __syncthreads();
        for (int i = t; i < n; i += SORT_T) {
            int sl = cur[i];
            unsigned pr = pairs[sl];
            int s = pr >> 9, d = pr & 511;
            if (marked[s] | marked[d]) continue;
            int pos = atomicAdd(&cntr[0], 1);
            nxt[pos] = (unsigned short)sl;
            unsigned long long k = g_ukey[base + sl];
            atomicMax(&best[s], k);
            if (d != s) atomicMax(&best[d], k);
        }
        __syncthreads();
        n = cntr[0];
        if (n == 0) break;
        for (int i = t; i < n; i += SORT_T) {
            int sl = nxt[i];
            unsigned pr = pairs[sl];
            int s = pr >> 9, d = pr & 511;
            unsigned long long k = g_ukey[base + sl];
            if (best[s] == k && best[d] == k) {      // dominant at both ends -> chosen
                marked[s] = 1; marked[d] = 1;
                int sG = src[base + sl], dG = dst[base + sl];
                int rep = min(sG, dG), oth = max(sG, dG);
                g_nscore[rep] = g_escore[base + sl];
                if (sG != dG) {
                    g_cluster[oth] = rep;
                    g_nvalid[oth] = 0;
                    g_partner[rep] = oth;
                }
            }
        }
        unsigned short* tmp = cur; cur = nxt; nxt = tmp;
        __syncthreads();
    }
}

// ----------------------------- fused pooling (no atomics) ----------------------
__global__ void k_pool(int F) {
    int tid = blockIdx.x * blockDim.x + threadIdx.x;
    if (tid >= NN * F) return;
    int i = tid / F, f = tid - i * F;
    float v = 0.f;
    if (g_nvalid[i]) {
        v = g_C[tid];
        int p = g_partner[i];
        if (p >= 0) v += g_C[p * F + f];
        v = fmaxf(v * g_nscore[i], 0.f);
    }
    g_X[tid] = v;
}

// ----------------------------- coalesce edges to next level -------------------
__global__ void __launch_bounds__(SORT_T, 1) k_coalesce(int inA) {
    extern __shared__ char smraw[];
    int g = blockIdx.x, base = g * CAP, t = threadIdx.x;
    const int* src = inA ? g_srcA : g_srcB;
    const int* dst = inA ? g_dstA : g_dstB;
    const int* cntp = inA ? g_cntA : g_cntB;
    int* osrc = inA ? g_srcB : g_srcA;
    int* odst = inA ? g_dstB : g_dstA;
    int* ocnt = inA ? g_cntB : g_cntA;
    int cnt = cntp[g]; if (cnt > CAP) cnt = CAP;

    unsigned long long keys[SORT_I];
#pragma unroll
    for (int i = 0; i < SORT_I; i++) {
        int slot = t * SORT_I + i;
        if (slot < cnt) {
            int ns = g_cluster[src[base + slot]] & (PER - 1);
            int nd = g_cluster[dst[base + slot]] & (PER - 1);
            keys[i] = ((unsigned long long)(unsigned)((ns << 9) | nd) << CAPB) | (unsigned)slot;
        } else keys[i] = (1ull << 32);   // pad: pair-field = 2^18, sorts last
    }
    {
        typename SortT64::TempStorage& temp =
            *reinterpret_cast<typename SortT64::TempStorage*>(smraw);
        SortT64(temp).Sort(keys, CAPB, 33);
    }
    __syncthreads();
    unsigned long long* lastk = (unsigned long long*)smraw;          // SORT_T
    int* scan = (int*)(smraw + SORT_T * sizeof(unsigned long long)); // SORT_T
    lastk[t] = keys[SORT_I - 1];
    __syncthreads();
    unsigned prevl = (t == 0) ? 0xFFFFFFFFu : (unsigned)(lastk[t - 1] >> CAPB);
    int flags[SORT_I]; int cl = 0;
#pragma unroll
    for (int i = 0; i < SORT_I; i++) {
        int r = t * SORT_I + i;
        unsigned lk = (unsigned)(keys[i] >> CAPB);
        bool f = (r < cnt) && (lk != prevl);
        flags[i] = f; cl += f; prevl = lk;
    }
    __syncthreads();
    scan[t] = cl;
    __syncthreads();
    for (int off = 1; off < SORT_T; off <<= 1) {
        int v = (t >= off) ? scan[t - off] : 0;
        __syncthreads();
        scan[t] += v;
        __syncthreads();
    }
    int pos = scan[t] - cl;
#pragma unroll
    for (int i = 0; i < SORT_I; i++) {
        if (flags[i]) {
            unsigned lk = (unsigned)(keys[i] >> CAPB);
            osrc[base + pos] = g * PER + ((lk >> 9) & 511);
            odst[base + pos] = g * PER + (lk & 511);
            g_eidx[base + pos] = pos;
            pos++;
        }
    }
    if (t == SORT_T - 1) ocnt[g] = scan[t];
}

// ----------------------------- GEMM (g_B = A @ W), f32x2 + LDS.128 -------------
__global__ void k_gemm(const float* __restrict__ Ax, int K, int Nc, const float* __restrict__ W) {
    const float* A = Ax ? Ax : g_X;
    __shared__ float As[16][68];     // kk-major: stride 272B (16B-aligned), 2-way store conflicts
    __shared__ float Bs[16][68];
    int t = threadIdx.x;
    int bm = blockIdx.y * 64, bn = blockIdx.x * 64;
    int tm = (t >> 4) << 2, tn = (t & 15) << 2;
    unsigned long long acc2[4][2];
#pragma unroll
    for (int i = 0; i < 4; i++) { acc2[i][0] = pack2(0.f, 0.f); acc2[i][1] = pack2(0.f, 0.f); }

    for (int k0 = 0; k0 < K; k0 += 16) {
#pragma unroll
        for (int i = 0; i < 4; i++) {
            int lin = t + i * 256;
            int m = lin >> 4, kk = lin & 15;
            As[kk][m] = (k0 + kk < K) ? A[(bm + m) * K + k0 + kk] : 0.f;
            int k2 = lin >> 6, n2 = lin & 63;
            Bs[k2][n2] = (k0 + k2 < K && bn + n2 < Nc) ? W[(k0 + k2) * Nc + bn + n2] : 0.f;
        }
        __syncthreads();
#pragma unroll
        for (int kk = 0; kk < 16; kk++) {
            float4 a4 = *(const float4*)&As[kk][tm];
            unsigned long long b0 = *(const unsigned long long*)&Bs[kk][tn];
            unsigned long long b1 = *(const unsigned long long*)&Bs[kk][tn + 2];
            float av[4] = {a4.x, a4.y, a4.z, a4.w};
#pragma unroll
            for (int i = 0; i < 4; i++) {
                unsigned long long ap = pack2(av[i], av[i]);
                acc2[i][0] = fma2(ap, b0, acc2[i][0]);
                acc2[i][1] = fma2(ap, b1, acc2[i][1]);
            }
        }
        __syncthreads();
    }
#pragma unroll
    for (int i = 0; i < 4; i++) {
        float v0, v1, v2, v3;
        unpack2(v0, v1, acc2[i][0]);
        unpack2(v2, v3, acc2[i][1]);
        float vv[4] = {v0, v1, v2, v3};
#pragma unroll
        for (int j = 0; j < 4; j++)
            if (bn + tn + j < Nc) g_B[(bm + tm + i) * Nc + bn + tn + j] = vv[j];
    }
}

// ----------------------------- readout ----------------------------------------
__global__ void k_maxpool() {
    int g = blockIdx.y;
    int f = blockIdx.x * 128 + threadIdx.x;
    if (f >= 600) return;
    float m = -FLT_MAX;
    for (int p = 0; p < PER; p++) {
        int i = g * PER + p;
        if (g_nvalid[i]) m = fmaxf(m, g_X[i * 600 + f]);
    }
    g_pool[g * 600 + f] = m;
}

__global__ void k_mlp(const float* __restrict__ L1w, const float* __restrict__ L1b,
                      const float* __restrict__ L2w, const float* __restrict__ L2b,
                      const float* __restrict__ L3w, const float* __restrict__ L3b,
                      float* __restrict__ out) {
    __shared__ float z1[200];
    __shared__ float z2[20];
    __shared__ float z3[4];
    int g = blockIdx.x, t = threadIdx.x;
    if (t < 200) {
        float a = L1b[t];
        for (int k = 0; k < 600; k++) a += g_pool[g * 600 + k] * L1w[k * 200 + t];
        z1[t] = fmaxf(a, 0.f);
    }
    __syncthreads();
    if (t < 20) {
        float a = L2b[t];
        for (int k = 0; k < 200; k++) a += z1[k] * L2w[k * 20 + t];
        z2[t] = fmaxf(a, 0.f);
    }
    __syncthreads();
    if (t < 4) {
        float a = L3b[t];
        for (int k = 0; k < 20; k++) a += z2[k] * L3w[k * 4 + t];
        z3[t] = fmaxf(a, 0.f);
    }
    __syncthreads();
    if (t == 0) {
        float m = fmaxf(fmaxf(z3[0], z3[1]), fmaxf(z3[2], z3[3]));
        float e0 = expf(z3[0] - m), e1 = expf(z3[1] - m);
        float e2 = expf(z3[2] - m), e3 = expf(z3[3] - m);
        float s = e0 + e1 + e2 + e3;
        out[g * 4 + 0] = e0 / s;
        out[g * 4 + 1] = e1 / s;
        out[g * 4 + 2] = e2 / s;
        out[g * 4 + 3] = e3 / s;
    }
}

// ----------------------------- host orchestration ------------------------------
extern "C" void kernel_launch(void* const* d_in, const int* in_sizes, int n_in,
                              void* d_out, int out_size) {
    (void)in_sizes; (void)n_in; (void)out_size;
    const float* x   = (const float*)d_in[0];
    const int*   ei  = (const int*)d_in[1];
    const float* W1  = (const float*)d_in[3];
    const float* b1  = (const float*)d_in[4];
    const float* W2  = (const float*)d_in[5];
    const float* b2  = (const float*)d_in[6];
    const float* W3  = (const float*)d_in[7];
    const float* b3  = (const float*)d_in[8];
    const float* P1w = (const float*)d_in[9];
    const float* P1b = (const float*)d_in[10];
    const float* P2w = (const float*)d_in[11];
    const float* P2b = (const float*)d_in[12];
    const float* P3w = (const float*)d_in[13];
    const float* P3b = (const float*)d_in[14];
    const float* L1w = (const float*)d_in[15];
    const float* L1b = (const float*)d_in[16];
    const float* L2w = (const float*)d_in[17];
    const float* L2b = (const float*)d_in[18];
    const float* L3w = (const float*)d_in[19];
    const float* L3b = (const float*)d_in[20];
    float* out = (float*)d_out;

    const size_t SMEM64 = sizeof(typename SortT64::TempStorage);
    size_t SMEM_DST = sizeof(typename SortT32::TempStorage);
    if (SMEM_DST < (size_t)CAP * 2) SMEM_DST = (size_t)CAP * 2;

    static cudaStream_t s1 = nullptr;
    static cudaEvent_t e_ing, e_sd1, e_sd2, e_sd3, e_m1, e_m2, e_p1, e_p2;
    if (!s1) {
        cudaStreamCreateWithFlags(&s1, cudaStreamNonBlocking);
        cudaEventCreateWithFlags(&e_ing, cudaEventDisableTiming);
        cudaEventCreateWithFlags(&e_sd1, cudaEventDisableTiming);
        cudaEventCreateWithFlags(&e_sd2, cudaEventDisableTiming);
        cudaEventCreateWithFlags(&e_sd3, cudaEventDisableTiming);
        cudaEventCreateWithFlags(&e_m1, cudaEventDisableTiming);
        cudaEventCreateWithFlags(&e_m2, cudaEventDisableTiming);
        cudaEventCreateWithFlags(&e_p1, cudaEventDisableTiming);
        cudaEventCreateWithFlags(&e_p2, cudaEventDisableTiming);
        cudaFuncSetAttribute(k_coalesce, cudaFuncAttributeMaxDynamicSharedMemorySize, (int)SMEM64);
        cudaFuncSetAttribute(k_sortdst,  cudaFuncAttributeMaxDynamicSharedMemorySize, (int)SMEM_DST);
        cudaFuncSetAttribute(k_matchdom, cudaFuncAttributeMaxDynamicSharedMemorySize, (int)MATCH_SMEM);
    }
    cudaStream_t s0 = 0;

    k_init0<<<64, 256, 0, s0>>>();
    k_ingest<<<EE / 256, 256, 0, s0>>>(ei);
    cudaEventRecord(e_ing, s0);
    cudaStreamWaitEvent(s1, e_ing, 0);

    // ---------------- Level 1 (edges in A) ----------------
    k_gemm<<<dim3(200 / 64 + 1, NN / 64), 256, 0, s0>>>(x, 107, 200, W1);
    k_sortdst<<<NGR, SORT_T, SMEM_DST, s1>>>(1);
    cudaEventRecord(e_sd1, s1);
    cudaStreamWaitEvent(s0, e_sd1, 0);
    k_aggcsr<<<dim3((200 + 31) / 32, NGR), 256, 0, s0>>>(200, b1);
    k_nodedot<<<(NN * 32) / 256, 256, 0, s0>>>(P1w, 200);
    k_maxden<<<(NN * 32) / 256, 256, 0, s0>>>(P1b);
    k_matchdom<<<NGR, SORT_T, MATCH_SMEM, s0>>>(1);
    cudaEventRecord(e_m1, s0);
    k_pool<<<(NN * 200 + 255) / 256, 256, 0, s0>>>(200);
    cudaEventRecord(e_p1, s0);
    cudaStreamWaitEvent(s1, e_m1, 0);
    k_coalesce<<<NGR, SORT_T, SMEM64, s1>>>(1);          // edges A -> B
    cudaStreamWaitEvent(s1, e_p1, 0);
    k_sortdst<<<NGR, SORT_T, SMEM_DST, s1>>>(0);         // level-2 CSR (overlaps gemm2)
    cudaEventRecord(e_sd2, s1);

    // ---------------- Level 2 (edges in B) ----------------
    k_gemm<<<dim3(400 / 64 + 1, NN / 64), 256, 0, s0>>>(nullptr, 200, 400, W2);
    cudaStreamWaitEvent(s0, e_sd2, 0);
    k_aggcsr<<<dim3((400 + 31) / 32, NGR), 256, 0, s0>>>(400, b2);
    k_nodedot<<<(NN * 32) / 256, 256, 0, s0>>>(P2w, 400);
    k_maxden<<<(NN * 32) / 256, 256, 0, s0>>>(P2b);
    k_matchdom<<<NGR, SORT_T, MATCH_SMEM, s0>>>(0);
    cudaEventRecord(e_m2, s0);
    k_pool<<<(NN * 400 + 255) / 256, 256, 0, s0>>>(400);
    cudaEventRecord(e_p2, s0);
    cudaStreamWaitEvent(s1, e_m2, 0);
    k_coalesce<<<NGR, SORT_T, SMEM64, s1>>>(0);          // edges B -> A
    cudaStreamWaitEvent(s1, e_p2, 0);
    k_sortdst<<<NGR, SORT_T, SMEM_DST, s1>>>(1);         // level-3 CSR (overlaps gemm3)
    cudaEventRecord(e_sd3, s1);

    // ---------------- Level 3 (edges in A; no coalesce needed) ----------------
    k_gemm<<<dim3(600 / 64 + 1, NN / 64), 256, 0, s0>>>(nullptr, 400, 600, W3);
    cudaStreamWaitEvent(s0, e_sd3, 0);
    k_aggcsr<<<dim3((600 + 31) / 32, NGR), 256, 0, s0>>>(600, b3);
    k_nodedot<<<(NN * 32) / 256, 256, 0, s0>>>(P3w, 600);
    k_maxden<<<(NN * 32) / 256, 256, 0, s0>>>(P3b);
    k_matchdom<<<NGR, SORT_T, MATCH_SMEM, s0>>>(1);
    k_pool<<<(NN * 600 + 255) / 256, 256, 0, s0>>>(600);

    k_maxpool<<<dim3(5, NGR), 128, 0, s0>>>();
    k_mlp<<<NGR, 256, 0, s0>>>(L1w, L1b, L2w, L2b, L3w, L3b, out);
}